// round 6
// baseline (speedup 1.0000x reference)
#include <cuda_runtime.h>
#include <math.h>
#include <stdint.h>

#define Vn 10000
#define Hn 512
#define On 512
#define Bn 256
#define Sn 256
#define N1 1536

#define NJ 16
#define NG 8
#define RB 32
#define PAD_ST 132
#define CLUSTER 16
// smem: sWgz[512*64] + sWh[512*32] + sSt[32*132] + zbuf[32*33] + hbuf[32*33]
#define SMEM_BYTES ((512*64 + 512*32 + 32*PAD_ST + 2*32*33) * 4)

// ---------------- scratch ----------------------------------------------------
__device__ float g_EmbW[(size_t)Vn * N1];
__device__ float g_embR[(size_t)Vn * Hn];      // tf32-rounded emb
__device__ float g_WxT [Hn * N1];              // tf32-rounded
__device__ float g_WgHt[Hn * 1024];
__device__ float g_WhHt[Hn * Hn];
__device__ float g_WoT [Hn * On];              // tf32-rounded
__device__ float g_h   [Bn * Hn];              // exact h (final step only)
__device__ float g_hR  [Bn * Hn];              // rounded h (A-operand exchange)
__device__ float g_rh  [Bn * Hn];              // rounded r*h
__device__ float g_Hs  [(size_t)Bn * Sn * Hn]; // rounded hidden states
// ---------------- helpers ----------------------------------------------------
__device__ __forceinline__ float f2tff(float f) {
    uint32_t u; asm("cvt.rna.tf32.f32 %0, %1;" : "=r"(u) : "f"(f));
    return __uint_as_float(u);
}
#define MMA_TF32(C, a0,a1,a2,a3, b0,b1)                                        \
    asm volatile("mma.sync.aligned.m16n8k8.row.col.f32.tf32.tf32.f32 "         \
                 "{%0,%1,%2,%3}, {%4,%5,%6,%7}, {%8,%9}, {%0,%1,%2,%3};"       \
                 : "+f"((C)[0]), "+f"((C)[1]), "+f"((C)[2]), "+f"((C)[3])      \
                 : "r"(a0), "r"(a1), "r"(a2), "r"(a3), "r"(b0), "r"(b1))

__device__ __forceinline__ uint32_t s2u(const void* p) {
    return (uint32_t)__cvta_generic_to_shared(p);
}
__device__ __forceinline__ void cp16(uint32_t dst, const void* src, bool pred) {
    int sz = pred ? 16 : 0;
    asm volatile("cp.async.cg.shared.global [%0], [%1], 16, %2;"
                 :: "r"(dst), "l"(src), "r"(sz) : "memory");
}
#define CP_COMMIT() asm volatile("cp.async.commit_group;" ::: "memory")
#define CP_WAIT1()  asm volatile("cp.async.wait_group 1;" ::: "memory")

#define CLUSTER_BAR() do {                                                   \
    asm volatile("fence.acq_rel.cluster;" ::: "memory");                     \
    asm volatile("barrier.cluster.arrive.aligned;" ::: "memory");            \
    asm volatile("barrier.cluster.wait.aligned;" ::: "memory");              \
} while (0)

// ---------------- weight packing ---------------------------------------------
__global__ void pack_weights(const float* __restrict__ Wg,
                             const float* __restrict__ Wh,
                             const float* __restrict__ Wo) {
    int idx = blockIdx.x * blockDim.x + threadIdx.x;
    const int s1 = Hn * N1, s2 = Hn * 1024, s3 = Hn * Hn, s4 = Hn * On;
    if (idx < s1) {
        int k = idx / N1, n = idx % N1;
        g_WxT[idx] = f2tff((n < 1024) ? Wg[n * 1024 + k] : Wh[(n - 1024) * 1024 + k]);
    } else if (idx < s1 + s2) {
        int r = idx - s1; int k = r / 1024, j = r % 1024;
        g_WgHt[r] = Wg[j * 1024 + 512 + k];
    } else if (idx < s1 + s2 + s3) {
        int r = idx - s1 - s2; int k = r / 512, j = r % 512;
        g_WhHt[r] = Wh[j * 1024 + 512 + k];
    } else if (idx < s1 + s2 + s3 + s4) {
        int r = idx - s1 - s2 - s3; int k = r / 512, o = r % 512;
        g_WoT[r] = f2tff(Wo[o * 512 + k]);
    }
}

__global__ void round_emb(const float* __restrict__ emb) {
    int i = blockIdx.x * blockDim.x + threadIdx.x;
    if (i < Vn * Hn) g_embR[i] = f2tff(emb[i]);
}

// ------- double-buffered tf32 GEMM: C[M,N] = A[M,K] @ Bt[K,N] (+bias) -------
__global__ void __launch_bounds__(256)
gemm_db(const float* __restrict__ A, const float* __restrict__ Bt,
        float* __restrict__ C, const float* __restrict__ bias,
        int M, int N, int K) {
    __shared__ float As[2][128 * 20];
    __shared__ float Bs[2][16 * 136];
    const int tid = threadIdx.x, w = tid >> 5, l = tid & 31;
    const int wm = w >> 2, wn = w & 3;
    const int mBase = blockIdx.y * 128, nBase = blockIdx.x * 128;

    const int ar = tid >> 1, ac = (tid & 1) * 8;
    const int br = tid >> 4, bc = (tid & 15) * 4;

    auto stage = [&](int s, int k0) {
        bool pA = (mBase + ar) < M;
        const float* srcA = &A[(size_t)(mBase + ar) * K + k0 + ac];
        cp16(s2u(&As[s][ar * 20 + ac]),     srcA,     pA);
        cp16(s2u(&As[s][ar * 20 + ac + 4]), srcA + 4, pA);
        const float* srcB = &Bt[(size_t)(k0 + br) * N + nBase + bc];
        cp16(s2u(&Bs[s][br * 136 + bc]),      srcB,      true);
        cp16(s2u(&Bs[s][br * 136 + bc + 64]), srcB + 64, true);
    };

    float acc[4][4][4] = {};
    const int nIter = K / 16;
    stage(0, 0); CP_COMMIT();
    for (int it = 0; it < nIter; it++) {
        if (it + 1 < nIter) stage((it + 1) & 1, (it + 1) * 16);
        CP_COMMIT();
        CP_WAIT1();
        __syncthreads();
        const float* as = As[it & 1];
        const float* bs = Bs[it & 1];
        #pragma unroll
        for (int ks = 0; ks < 2; ks++) {
            const int kk = ks * 8 + (l & 3);
            uint32_t bfr[4][2];
            #pragma unroll
            for (int nt = 0; nt < 4; nt++) {
                int n = wn * 32 + nt * 8 + (l >> 2);
                bfr[nt][0] = __float_as_uint(bs[kk * 136 + n]);
                bfr[nt][1] = __float_as_uint(bs[(kk + 4) * 136 + n]);
            }
            #pragma unroll
            for (int mt = 0; mt < 4; mt++) {
                int r = wm * 64 + mt * 16 + (l >> 2);
                uint32_t a0 = __float_as_uint(as[r * 20 + kk]);
                uint32_t a1 = __float_as_uint(as[(r + 8) * 20 + kk]);
                uint32_t a2 = __float_as_uint(as[r * 20 + kk + 4]);
                uint32_t a3 = __float_as_uint(as[(r + 8) * 20 + kk + 4]);
                #pragma unroll
                for (int nt = 0; nt < 4; nt++)
                    MMA_TF32(acc[mt][nt], a0, a1, a2, a3, bfr[nt][0], bfr[nt][1]);
            }
        }
        __syncthreads();
    }
    #pragma unroll
    for (int mt = 0; mt < 4; mt++) {
        #pragma unroll
        for (int nt = 0; nt < 4; nt++) {
            #pragma unroll
            for (int rr = 0; rr < 4; rr++) {
                int row = mBase + wm * 64 + mt * 16 + (l >> 2) + ((rr >= 2) ? 8 : 0);
                if (row >= M) continue;
                int col = nBase + wn * 32 + nt * 8 + (l & 3) * 2 + (rr & 1);
                float v = acc[mt][nt][rr];
                if (bias) v += bias[col];
                C[(size_t)row * N + col] = v;
            }
        }
    }
}

// ---------------- persistent clustered GRU recurrence ------------------------
__global__ void __launch_bounds__(256, 1)
gru_persistent(const int* __restrict__ x, const float* __restrict__ bg,
               const float* __restrict__ bh) {
    extern __shared__ float sm[];
    float* sWgz = sm;                           // [512][64] swizzled: n<32 -> r-cols, n>=32 -> z-cols
    float* sWh  = sWgz + 512 * 64;              // [512][32] swizzled
    float* sSt  = sWh + 512 * 32;               // [32][PAD_ST] staging
    float* zbuf = sSt + 32 * PAD_ST;            // [32][33]
    float* hbuf = zbuf + 32 * 33;               // [32][33] exact owned h slice

    const int jt  = blockIdx.x & 15;
    const int g   = blockIdx.x >> 4;
    const int tid = threadIdx.x;
    const int w   = tid >> 5, l = tid & 31;
    const int mt  = w & 1;
    const int wn  = w >> 1;                     // 0..3
    const int bBase = g * RB;

    // weight slices: combined [r-cols | z-cols] for this CTA's 32 j-columns
    for (int i = tid; i < 512 * 64; i += 256) {
        int k = i >> 6, c = i & 63;
        int gcol = (c < 32) ? (512 + jt * 32 + c) : (jt * 32 + c - 32);
        sWgz[k * 64 + (c ^ ((k & 3) * 8))] = f2tff(g_WgHt[k * 1024 + gcol]);
    }
    for (int i = tid; i < 512 * 32; i += 256) {
        int k = i >> 5, c = i & 31;
        sWh[k * 32 + (c ^ ((k & 3) * 8))] = f2tff(g_WhHt[k * 512 + jt * 32 + c]);
    }
    for (int i = tid; i < 32 * 33; i += 256) { zbuf[i] = 0.f; hbuf[i] = 0.f; }
    __syncthreads();

    const int row0 = bBase + mt * 16 + (l >> 2);
    // biases for this lane's fixed columns
    float bgv[4], bhv[2];
    #pragma unroll
    for (int ti = 0; ti < 2; ti++)
        #pragma unroll
        for (int p = 0; p < 2; p++) {
            int n = wn * 16 + ti * 8 + (l & 3) * 2 + p;
            int gcol = (n < 32) ? (512 + jt * 32 + n) : (jt * 32 + n - 32);
            bgv[ti * 2 + p] = bg[gcol];
        }
    #pragma unroll
    for (int p = 0; p < 2; p++)
        bhv[p] = bh[jt * 32 + wn * 8 + (l & 3) * 2 + p];

    int srow[4], skq[4];
    #pragma unroll
    for (int j = 0; j < 4; j++) {
        int i = tid + j * 256;
        srow[j] = i >> 5; skq[j] = (i & 31) * 4;
    }

    float hreg[4] = {0.f, 0.f, 0.f, 0.f};       // owned h values (exact)

    for (int t = 0; t < Sn; t++) {
        const int tok0 = __ldg(&x[row0 * Sn + t]);
        const int tok1 = __ldg(&x[(row0 + 8) * Sn + t]);

        // epilogue operand prefetch (EmbW rows; hv from smem)
        float ew1[8], hv1[8], ew2[4];
        #pragma unroll
        for (int ti = 0; ti < 2; ti++)
            #pragma unroll
            for (int rr = 0; rr < 4; rr++) {
                int tok = (rr < 2) ? tok0 : tok1;
                int n = wn * 16 + ti * 8 + (l & 3) * 2 + (rr & 1);
                int gcol = (n < 32) ? (512 + jt * 32 + n) : (jt * 32 + n - 32);
                ew1[ti * 4 + rr] = __ldg(&g_EmbW[(size_t)tok * N1 + gcol]);
                int rl = mt * 16 + (l >> 2) + ((rr >= 2) ? 8 : 0);
                hv1[ti * 4 + rr] = hbuf[rl * 33 + (n & 31)];
            }
        #pragma unroll
        for (int rr = 0; rr < 4; rr++) {
            int tok = (rr < 2) ? tok0 : tok1;
            int n2 = wn * 8 + (l & 3) * 2 + (rr & 1);
            ew2[rr] = __ldg(&g_EmbW[(size_t)tok * N1 + 1024 + jt * 32 + n2]);
        }

        // ========== phase 1: r|z slice = h @ sWgz ==========
        float acc[8] = {};
        {
            float4 pf[4];
            #pragma unroll
            for (int j = 0; j < 4; j++)
                pf[j] = __ldcg((const float4*)&g_hR[(bBase + srow[j]) * 512 + skq[j]]);
            for (int pass = 0; pass < 4; pass++) {
                const int kb = pass * 128;
                __syncthreads();
                #pragma unroll
                for (int j = 0; j < 4; j++)
                    *(float4*)&sSt[srow[j] * PAD_ST + skq[j]] = pf[j];  // pre-rounded
                if (pass < 3) {
                    #pragma unroll
                    for (int j = 0; j < 4; j++)
                        pf[j] = __ldcg((const float4*)&g_hR[(bBase + srow[j]) * 512
                                                            + kb + 128 + skq[j]]);
                }
                __syncthreads();
                #pragma unroll
                for (int ks = 0; ks < 16; ks++) {
                    const float* ap = &sSt[(mt * 16 + (l >> 2)) * PAD_ST + ks * 8 + (l & 3)];
                    uint32_t a0 = __float_as_uint(ap[0]);
                    uint32_t a1 = __float_as_uint(ap[8 * PAD_ST]);
                    uint32_t a2 = __float_as_uint(ap[4]);
                    uint32_t a3 = __float_as_uint(ap[8 * PAD_ST + 4]);
                    const int kg = kb + ks * 8 + (l & 3);
                    const int sw = (kg & 3) * 8;
                    #pragma unroll
                    for (int ti = 0; ti < 2; ti++) {
                        int n = (wn * 16 + ti * 8 + (l >> 2)) ^ sw;
                        uint32_t b0 = __float_as_uint(sWgz[kg * 64 + n]);
                        uint32_t b1 = __float_as_uint(sWgz[(kg + 4) * 64 + n]);
                        MMA_TF32(acc + ti * 4, a0, a1, a2, a3, b0, b1);
                    }
                }
            }
        }
        // epilogue: wn<2 -> r -> rh to global; wn>=2 -> z -> smem
        #pragma unroll
        for (int ti = 0; ti < 2; ti++) {
            #pragma unroll
            for (int rr = 0; rr < 4; rr++) {
                int row = (rr < 2) ? row0 : (row0 + 8);
                int rl  = mt * 16 + (l >> 2) + ((rr >= 2) ? 8 : 0);
                int n = wn * 16 + ti * 8 + (l & 3) * 2 + (rr & 1);
                float gv = acc[ti * 4 + rr] + ew1[ti * 4 + rr] + bgv[ti * 2 + (rr & 1)];
                float s = 1.f / (1.f + __expf(-gv));
                if (n < 32) {
                    __stcg(&g_rh[row * 512 + jt * 32 + n], f2tff(s * hv1[ti * 4 + rr]));
                } else {
                    zbuf[rl * 33 + (n - 32)] = s;
                }
            }
        }
        CLUSTER_BAR();

        // ========== phase 2: cand slice = rh @ sWh ==========
        float acc2[4] = {};
        {
            float4 pf[4];
            #pragma unroll
            for (int j = 0; j < 4; j++)
                pf[j] = __ldcg((const float4*)&g_rh[(bBase + srow[j]) * 512 + skq[j]]);
            for (int pass = 0; pass < 4; pass++) {
                const int kb = pass * 128;
                __syncthreads();
                #pragma unroll
                for (int j = 0; j < 4; j++)
                    *(float4*)&sSt[srow[j] * PAD_ST + skq[j]] = pf[j];
                if (pass < 3) {
                    #pragma unroll
                    for (int j = 0; j < 4; j++)
                        pf[j] = __ldcg((const float4*)&g_rh[(bBase + srow[j]) * 512
                                                            + kb + 128 + skq[j]]);
                }
                __syncthreads();
                #pragma unroll
                for (int ks = 0; ks < 16; ks++) {
                    const float* ap = &sSt[(mt * 16 + (l >> 2)) * PAD_ST + ks * 8 + (l & 3)];
                    uint32_t a0 = __float_as_uint(ap[0]);
                    uint32_t a1 = __float_as_uint(ap[8 * PAD_ST]);
                    uint32_t a2 = __float_as_uint(ap[4]);
                    uint32_t a3 = __float_as_uint(ap[8 * PAD_ST + 4]);
                    const int kg = kb + ks * 8 + (l & 3);
                    const int sw = (kg & 3) * 8;
                    int n = (wn * 8 + (l >> 2)) ^ sw;
                    uint32_t b0 = __float_as_uint(sWh[kg * 32 + n]);
                    uint32_t b1 = __float_as_uint(sWh[(kg + 4) * 32 + n]);
                    MMA_TF32(acc2, a0, a1, a2, a3, b0, b1);
                }
            }
        }
        __syncthreads();   // zbuf reads below vs (nothing pending) + hbuf write ordering
        #pragma unroll
        for (int rr = 0; rr < 4; rr++) {
            int row = (rr < 2) ? row0 : (row0 + 8);
            int rl  = mt * 16 + (l >> 2) + ((rr >= 2) ? 8 : 0);
            int n2  = wn * 8 + (l & 3) * 2 + (rr & 1);
            int col = jt * 32 + n2;
            float cand = tanhf(acc2[rr] + ew2[rr] + bhv[rr & 1]);
            float zz = zbuf[rl * 33 + n2];
            float hn = fmaf(zz, cand - hreg[rr], hreg[rr]);
            hreg[rr] = hn;
            hbuf[rl * 33 + n2] = hn;
            float hr = f2tff(hn);
            __stcg(&g_hR[row * 512 + col], hr);
            __stcg(&g_Hs[((size_t)row * Sn + t) * 512 + col], hr);
            if (t == Sn - 1) g_h[row * 512 + col] = hn;
        }
        CLUSTER_BAR();
    }
}

// ---------------- tiny helpers ----------------------------------------------
__global__ void zero_misc() {
    int i = blockIdx.x * blockDim.x + threadIdx.x;
    if (i < Bn * Hn) { g_h[i] = 0.f; g_hR[i] = 0.f; }
}
__global__ void copy_h(float* __restrict__ out) {
    int i = blockIdx.x * blockDim.x + threadIdx.x;
    if (i < Bn * Hn) out[i] = g_h[i];
}

// ---------------- entry ------------------------------------------------------
extern "C" void kernel_launch(void* const* d_in, const int* in_sizes, int n_in,
                              void* d_out, int out_size) {
    const int*   x   = (const int*)  d_in[0];
    const float* emb = (const float*)d_in[1];
    const float* Wg  = (const float*)d_in[2];
    const float* bg  = (const float*)d_in[3];
    const float* Wh  = (const float*)d_in[4];
    const float* bh  = (const float*)d_in[5];
    const float* Wo  = (const float*)d_in[6];
    const float* bo  = (const float*)d_in[7];
    float* out = (float*)d_out;

    float *pEmbW, *pEmbR, *pWxT, *pWoT, *pHs;
    cudaGetSymbolAddress((void**)&pEmbW, g_EmbW);
    cudaGetSymbolAddress((void**)&pEmbR, g_embR);
    cudaGetSymbolAddress((void**)&pWxT,  g_WxT);
    cudaGetSymbolAddress((void**)&pWoT,  g_WoT);
    cudaGetSymbolAddress((void**)&pHs,   g_Hs);

    cudaFuncSetAttribute(gru_persistent,
                         cudaFuncAttributeMaxDynamicSharedMemorySize, SMEM_BYTES);
    cudaFuncSetAttribute(gru_persistent,
                         cudaFuncAttributeNonPortableClusterSizeAllowed, 1);

    pack_weights<<<7168, 256>>>(Wg, Wh, Wo);
    round_emb<<<(Vn * Hn + 255) / 256, 256>>>(emb);
    gemm_db<<<dim3(N1 / 128, (Vn + 127) / 128), 256>>>(pEmbR, pWxT, pEmbW, nullptr,
                                                       Vn, N1, Hn);
    zero_misc<<<(Bn * Hn + 255) / 256, 256>>>();

    {
        cudaLaunchConfig_t cfg = {};
        cfg.gridDim = dim3(NG * CLUSTER, 1, 1);
        cfg.blockDim = dim3(256, 1, 1);
        cfg.dynamicSmemBytes = SMEM_BYTES;
        cfg.stream = 0;
        cudaLaunchAttribute at[1];
        at[0].id = cudaLaunchAttributeClusterDimension;
        at[0].val.clusterDim.x = CLUSTER;
        at[0].val.clusterDim.y = 1;
        at[0].val.clusterDim.z = 1;
        cfg.attrs = at;
        cfg.numAttrs = 1;
        cudaLaunchKernelEx(&cfg, gru_persistent, x, bg, bh);
    }

    gemm_db<<<dim3(On / 128, (Bn * Sn) / 128), 256>>>(pHs, pWoT, out + Bn * Hn, bo,
                                                      Bn * Sn, On, Hn);
    copy_h<<<(Bn * Hn + 255) / 256, 256>>>(out);
}

// round 8
// speedup vs baseline: 1.3053x; 1.3053x over previous
#include <cuda_runtime.h>
#include <math.h>
#include <stdint.h>

#define Vn 10000
#define Hn 512
#define On 512
#define Bn 256
#define Sn 256
#define N1 1536

#define NJ 16
#define NG 8
#define RB 32
#define PAD_ST 132
// smem: sWgz[512*64] + sWh[512*32] + sSt[32*132] + zbuf[32*33] + hbuf[32*33]
#define SMEM_BYTES ((512*64 + 512*32 + 32*PAD_ST + 2*32*33) * 4)

// ---------------- scratch ----------------------------------------------------
__device__ float g_EmbW[(size_t)Vn * N1];
__device__ float g_embR[(size_t)Vn * Hn];      // tf32-rounded emb
__device__ float g_WxT [Hn * N1];              // tf32-rounded
__device__ float g_WgHt[Hn * 1024];
__device__ float g_WhHt[Hn * Hn];
__device__ float g_WoT [Hn * On];              // tf32-rounded
__device__ float g_h   [Bn * Hn];              // exact h (final step only)
__device__ float g_hR  [Bn * Hn];              // rounded h (A-operand exchange)
__device__ float g_rh  [Bn * Hn];              // rounded r*h
__device__ float g_Hs  [(size_t)Bn * Sn * Hn]; // rounded hidden states
__device__ __align__(64) int g_flag1[NG][16];  // phase1 completion per CTA
__device__ __align__(64) int g_flag2[NG][16];  // phase2 completion per CTA

// ---------------- helpers ----------------------------------------------------
__device__ __forceinline__ float f2tff(float f) {
    uint32_t u; asm("cvt.rna.tf32.f32 %0, %1;" : "=r"(u) : "f"(f));
    return __uint_as_float(u);
}
#define MMA_TF32(C, a0,a1,a2,a3, b0,b1)                                        \
    asm volatile("mma.sync.aligned.m16n8k8.row.col.f32.tf32.tf32.f32 "         \
                 "{%0,%1,%2,%3}, {%4,%5,%6,%7}, {%8,%9}, {%0,%1,%2,%3};"       \
                 : "+f"((C)[0]), "+f"((C)[1]), "+f"((C)[2]), "+f"((C)[3])      \
                 : "r"(a0), "r"(a1), "r"(a2), "r"(a3), "r"(b0), "r"(b1))

__device__ __forceinline__ uint32_t s2u(const void* p) {
    return (uint32_t)__cvta_generic_to_shared(p);
}
__device__ __forceinline__ void cp16(uint32_t dst, const void* src, bool pred) {
    int sz = pred ? 16 : 0;
    asm volatile("cp.async.cg.shared.global [%0], [%1], 16, %2;"
                 :: "r"(dst), "l"(src), "r"(sz) : "memory");
}
#define CP_COMMIT() asm volatile("cp.async.commit_group;" ::: "memory")
#define CP_WAIT1()  asm volatile("cp.async.wait_group 1;" ::: "memory")

// -------- proven sync primitives (same class as R5's working barrier) --------
__device__ __forceinline__ int ld_acq(const int* p) {
    int v; asm volatile("ld.acquire.gpu.global.s32 %0, [%1];" : "=r"(v) : "l"(p) : "memory");
    return v;
}
// wait until 4 contiguous flags reach target
__device__ __forceinline__ void wait4(const int* f, int target) {
    while (ld_acq(f + 0) < target) {}
    while (ld_acq(f + 1) < target) {}
    while (ld_acq(f + 2) < target) {}
    while (ld_acq(f + 3) < target) {}
}
// publish (call from tid==0 after __syncthreads())
__device__ __forceinline__ void flag_store(int* f, int v) {
    __threadfence();
    atomicExch(f, v);
}

// ---------------- weight packing ---------------------------------------------
__global__ void pack_weights(const float* __restrict__ Wg,
                             const float* __restrict__ Wh,
                             const float* __restrict__ Wo) {
    int idx = blockIdx.x * blockDim.x + threadIdx.x;
    const int s1 = Hn * N1, s2 = Hn * 1024, s3 = Hn * Hn, s4 = Hn * On;
    if (idx < s1) {
        int k = idx / N1, n = idx % N1;
        g_WxT[idx] = f2tff((n < 1024) ? Wg[n * 1024 + k] : Wh[(n - 1024) * 1024 + k]);
    } else if (idx < s1 + s2) {
        int r = idx - s1; int k = r / 1024, j = r % 1024;
        g_WgHt[r] = Wg[j * 1024 + 512 + k];
    } else if (idx < s1 + s2 + s3) {
        int r = idx - s1 - s2; int k = r / 512, j = r % 512;
        g_WhHt[r] = Wh[j * 1024 + 512 + k];
    } else if (idx < s1 + s2 + s3 + s4) {
        int r = idx - s1 - s2 - s3; int k = r / 512, o = r % 512;
        g_WoT[r] = f2tff(Wo[o * 512 + k]);
    }
}

__global__ void round_emb(const float* __restrict__ emb) {
    int i = blockIdx.x * blockDim.x + threadIdx.x;
    if (i < Vn * Hn) g_embR[i] = f2tff(emb[i]);
}

// ------- double-buffered tf32 GEMM: C[M,N] = A[M,K] @ Bt[K,N] (+bias) -------
__global__ void __launch_bounds__(256)
gemm_db(const float* __restrict__ A, const float* __restrict__ Bt,
        float* __restrict__ C, const float* __restrict__ bias,
        int M, int N, int K) {
    __shared__ float As[2][128 * 20];
    __shared__ float Bs[2][16 * 136];
    const int tid = threadIdx.x, w = tid >> 5, l = tid & 31;
    const int wm = w >> 2, wn = w & 3;
    const int mBase = blockIdx.y * 128, nBase = blockIdx.x * 128;

    const int ar = tid >> 1, ac = (tid & 1) * 8;
    const int br = tid >> 4, bc = (tid & 15) * 4;

    auto stage = [&](int s, int k0) {
        bool pA = (mBase + ar) < M;
        const float* srcA = &A[(size_t)(mBase + ar) * K + k0 + ac];
        cp16(s2u(&As[s][ar * 20 + ac]),     srcA,     pA);
        cp16(s2u(&As[s][ar * 20 + ac + 4]), srcA + 4, pA);
        const float* srcB = &Bt[(size_t)(k0 + br) * N + nBase + bc];
        cp16(s2u(&Bs[s][br * 136 + bc]),      srcB,      true);
        cp16(s2u(&Bs[s][br * 136 + bc + 64]), srcB + 64, true);
    };

    float acc[4][4][4] = {};
    const int nIter = K / 16;
    stage(0, 0); CP_COMMIT();
    for (int it = 0; it < nIter; it++) {
        if (it + 1 < nIter) stage((it + 1) & 1, (it + 1) * 16);
        CP_COMMIT();
        CP_WAIT1();
        __syncthreads();
        const float* as = As[it & 1];
        const float* bs = Bs[it & 1];
        #pragma unroll
        for (int ks = 0; ks < 2; ks++) {
            const int kk = ks * 8 + (l & 3);
            uint32_t bfr[4][2];
            #pragma unroll
            for (int nt = 0; nt < 4; nt++) {
                int n = wn * 32 + nt * 8 + (l >> 2);
                bfr[nt][0] = __float_as_uint(bs[kk * 136 + n]);
                bfr[nt][1] = __float_as_uint(bs[(kk + 4) * 136 + n]);
            }
            #pragma unroll
            for (int mt = 0; mt < 4; mt++) {
                int r = wm * 64 + mt * 16 + (l >> 2);
                uint32_t a0 = __float_as_uint(as[r * 20 + kk]);
                uint32_t a1 = __float_as_uint(as[(r + 8) * 20 + kk]);
                uint32_t a2 = __float_as_uint(as[r * 20 + kk + 4]);
                uint32_t a3 = __float_as_uint(as[(r + 8) * 20 + kk + 4]);
                #pragma unroll
                for (int nt = 0; nt < 4; nt++)
                    MMA_TF32(acc[mt][nt], a0, a1, a2, a3, bfr[nt][0], bfr[nt][1]);
            }
        }
        __syncthreads();
    }
    #pragma unroll
    for (int mt = 0; mt < 4; mt++) {
        #pragma unroll
        for (int nt = 0; nt < 4; nt++) {
            #pragma unroll
            for (int rr = 0; rr < 4; rr++) {
                int row = mBase + wm * 64 + mt * 16 + (l >> 2) + ((rr >= 2) ? 8 : 0);
                if (row >= M) continue;
                int col = nBase + wn * 32 + nt * 8 + (l & 3) * 2 + (rr & 1);
                float v = acc[mt][nt][rr];
                if (bias) v += bias[col];
                C[(size_t)row * N + col] = v;
            }
        }
    }
}

// ---------------- persistent GRU recurrence (dataflow flags) -----------------
__global__ void __launch_bounds__(256, 1)
gru_persistent(const int* __restrict__ x, const float* __restrict__ bg,
               const float* __restrict__ bh) {
    extern __shared__ float sm[];
    float* sWgz = sm;                           // [512][64]: n<32 r-cols, n>=32 z-cols
    float* sWh  = sWgz + 512 * 64;              // [512][32]
    float* sSt  = sWh + 512 * 32;               // [32][PAD_ST]
    float* zbuf = sSt + 32 * PAD_ST;            // [32][33]
    float* hbuf = zbuf + 32 * 33;               // [32][33]

    const int jt  = blockIdx.x & 15;
    const int g   = blockIdx.x >> 4;
    const int tid = threadIdx.x;
    const int w   = tid >> 5, l = tid & 31;
    const int mt  = w & 1;
    const int wn  = w >> 1;
    const int bBase = g * RB;

    for (int i = tid; i < 512 * 64; i += 256) {
        int k = i >> 6, c = i & 63;
        int gcol = (c < 32) ? (512 + jt * 32 + c) : (jt * 32 + c - 32);
        sWgz[k * 64 + (c ^ ((k & 3) * 8))] = f2tff(g_WgHt[k * 1024 + gcol]);
    }
    for (int i = tid; i < 512 * 32; i += 256) {
        int k = i >> 5, c = i & 31;
        sWh[k * 32 + (c ^ ((k & 3) * 8))] = f2tff(g_WhHt[k * 512 + jt * 32 + c]);
    }
    for (int i = tid; i < 32 * 33; i += 256) { zbuf[i] = 0.f; hbuf[i] = 0.f; }
    __syncthreads();

    const int row0 = bBase + mt * 16 + (l >> 2);
    float bgv[4], bhv[2];
    #pragma unroll
    for (int ti = 0; ti < 2; ti++)
        #pragma unroll
        for (int p = 0; p < 2; p++) {
            int n = wn * 16 + ti * 8 + (l & 3) * 2 + p;
            int gcol = (n < 32) ? (512 + jt * 32 + n) : (jt * 32 + n - 32);
            bgv[ti * 2 + p] = bg[gcol];
        }
    #pragma unroll
    for (int p = 0; p < 2; p++)
        bhv[p] = bh[jt * 32 + wn * 8 + (l & 3) * 2 + p];

    int srow[4], skq[4];
    #pragma unroll
    for (int j = 0; j < 4; j++) {
        int i = tid + j * 256;
        srow[j] = i >> 5; skq[j] = (i & 31) * 4;
    }

    float hreg[4] = {0.f, 0.f, 0.f, 0.f};

    for (int t = 0; t < Sn; t++) {
        const int tok0 = __ldg(&x[row0 * Sn + t]);
        const int tok1 = __ldg(&x[(row0 + 8) * Sn + t]);

        float ew1[8], hv1[8], ew2[4];
        #pragma unroll
        for (int ti = 0; ti < 2; ti++)
            #pragma unroll
            for (int rr = 0; rr < 4; rr++) {
                int tok = (rr < 2) ? tok0 : tok1;
                int n = wn * 16 + ti * 8 + (l & 3) * 2 + (rr & 1);
                int gcol = (n < 32) ? (512 + jt * 32 + n) : (jt * 32 + n - 32);
                ew1[ti * 4 + rr] = __ldg(&g_EmbW[(size_t)tok * N1 + gcol]);
                int rl = mt * 16 + (l >> 2) + ((rr >= 2) ? 8 : 0);
                hv1[ti * 4 + rr] = hbuf[rl * 33 + (n & 31)];
            }
        #pragma unroll
        for (int rr = 0; rr < 4; rr++) {
            int tok = (rr < 2) ? tok0 : tok1;
            int n2 = wn * 8 + (l & 3) * 2 + (rr & 1);
            ew2[rr] = __ldg(&g_EmbW[(size_t)tok * N1 + 1024 + jt * 32 + n2]);
        }

        // ========== phase 1: (r|z) = h @ sWgz.  A = g_hR, producers flag2>=t ==
        float acc[8] = {};
        {
            float4 pf[4];
            wait4(&g_flag2[g][0], t);
            #pragma unroll
            for (int j = 0; j < 4; j++)
                pf[j] = __ldcg((const float4*)&g_hR[(bBase + srow[j]) * 512 + skq[j]]);
            for (int pass = 0; pass < 4; pass++) {
                const int kb = pass * 128;
                __syncthreads();
                #pragma unroll
                for (int j = 0; j < 4; j++)
                    *(float4*)&sSt[srow[j] * PAD_ST + skq[j]] = pf[j];
                if (pass < 3) {
                    wait4(&g_flag2[g][4 * (pass + 1)], t);
                    #pragma unroll
                    for (int j = 0; j < 4; j++)
                        pf[j] = __ldcg((const float4*)&g_hR[(bBase + srow[j]) * 512
                                                            + kb + 128 + skq[j]]);
                }
                __syncthreads();
                #pragma unroll
                for (int ks = 0; ks < 16; ks++) {
                    const float* ap = &sSt[(mt * 16 + (l >> 2)) * PAD_ST + ks * 8 + (l & 3)];
                    uint32_t a0 = __float_as_uint(ap[0]);
                    uint32_t a1 = __float_as_uint(ap[8 * PAD_ST]);
                    uint32_t a2 = __float_as_uint(ap[4]);
                    uint32_t a3 = __float_as_uint(ap[8 * PAD_ST + 4]);
                    const int kg = kb + ks * 8 + (l & 3);
                    const int sw = (kg & 3) * 8;
                    #pragma unroll
                    for (int ti = 0; ti < 2; ti++) {
                        int n = (wn * 16 + ti * 8 + (l >> 2)) ^ sw;
                        uint32_t b0 = __float_as_uint(sWgz[kg * 64 + n]);
                        uint32_t b1 = __float_as_uint(sWgz[(kg + 4) * 64 + n]);
                        MMA_TF32(acc + ti * 4, a0, a1, a2, a3, b0, b1);
                    }
                }
            }
        }
        #pragma unroll
        for (int ti = 0; ti < 2; ti++) {
            #pragma unroll
            for (int rr = 0; rr < 4; rr++) {
                int row = (rr < 2) ? row0 : (row0 + 8);
                int rl  = mt * 16 + (l >> 2) + ((rr >= 2) ? 8 : 0);
                int n = wn * 16 + ti * 8 + (l & 3) * 2 + (rr & 1);
                float gv = acc[ti * 4 + rr] + ew1[ti * 4 + rr] + bgv[ti * 2 + (rr & 1)];
                float s = 1.f / (1.f + __expf(-gv));
                if (n < 32) {
                    __stcg(&g_rh[row * 512 + jt * 32 + n], f2tff(s * hv1[ti * 4 + rr]));
                } else {
                    zbuf[rl * 33 + (n - 32)] = s;
                }
            }
        }
        __syncthreads();
        if (tid == 0) flag_store(&g_flag1[g][jt], t + 1);

        // ========== phase 2: cand = rh @ sWh.  A = g_rh, producers flag1>=t+1 =
        float acc2[4] = {};
        {
            float4 pf[4];
            wait4(&g_flag1[g][0], t + 1);
            #pragma unroll
            for (int j = 0; j < 4; j++)
                pf[j] = __ldcg((const float4*)&g_rh[(bBase + srow[j]) * 512 + skq[j]]);
            for (int pass = 0; pass < 4; pass++) {
                const int kb = pass * 128;
                __syncthreads();
                #pragma unroll
                for (int j = 0; j < 4; j++)
                    *(float4*)&sSt[srow[j] * PAD_ST + skq[j]] = pf[j];
                if (pass < 3) {
                    wait4(&g_flag1[g][4 * (pass + 1)], t + 1);
                    #pragma unroll
                    for (int j = 0; j < 4; j++)
                        pf[j] = __ldcg((const float4*)&g_rh[(bBase + srow[j]) * 512
                                                            + kb + 128 + skq[j]]);
                }
                __syncthreads();
                #pragma unroll
                for (int ks = 0; ks < 16; ks++) {
                    const float* ap = &sSt[(mt * 16 + (l >> 2)) * PAD_ST + ks * 8 + (l & 3)];
                    uint32_t a0 = __float_as_uint(ap[0]);
                    uint32_t a1 = __float_as_uint(ap[8 * PAD_ST]);
                    uint32_t a2 = __float_as_uint(ap[4]);
                    uint32_t a3 = __float_as_uint(ap[8 * PAD_ST + 4]);
                    const int kg = kb + ks * 8 + (l & 3);
                    const int sw = (kg & 3) * 8;
                    int n = (wn * 8 + (l >> 2)) ^ sw;
                    uint32_t b0 = __float_as_uint(sWh[kg * 32 + n]);
                    uint32_t b1 = __float_as_uint(sWh[(kg + 4) * 32 + n]);
                    MMA_TF32(acc2, a0, a1, a2, a3, b0, b1);
                }
            }
        }
        __syncthreads();   // order phase1's zbuf writes / this phase's sSt reads
        #pragma unroll
        for (int rr = 0; rr < 4; rr++) {
            int row = (rr < 2) ? row0 : (row0 + 8);
            int rl  = mt * 16 + (l >> 2) + ((rr >= 2) ? 8 : 0);
            int n2  = wn * 8 + (l & 3) * 2 + (rr & 1);
            int col = jt * 32 + n2;
            float cand = tanhf(acc2[rr] + ew2[rr] + bhv[rr & 1]);
            float zz = zbuf[rl * 33 + n2];
            float hn = fmaf(zz, cand - hreg[rr], hreg[rr]);
            hreg[rr] = hn;
            hbuf[rl * 33 + n2] = hn;
            float hr = f2tff(hn);
            __stcg(&g_hR[row * 512 + col], hr);
            __stcg(&g_Hs[((size_t)row * Sn + t) * 512 + col], hr);
            if (t == Sn - 1) g_h[row * 512 + col] = hn;
        }
        __syncthreads();
        if (tid == 0) flag_store(&g_flag2[g][jt], t + 1);
    }
}

// ---------------- tiny helpers ----------------------------------------------
__global__ void zero_misc() {
    int i = blockIdx.x * blockDim.x + threadIdx.x;
    if (i < Bn * Hn) { g_h[i] = 0.f; g_hR[i] = 0.f; }
    if (i < NG * 16) { g_flag1[i >> 4][i & 15] = 0; g_flag2[i >> 4][i & 15] = 0; }
}
__global__ void copy_h(float* __restrict__ out) {
    int i = blockIdx.x * blockDim.x + threadIdx.x;
    if (i < Bn * Hn) out[i] = g_h[i];
}

// ---------------- entry ------------------------------------------------------
extern "C" void kernel_launch(void* const* d_in, const int* in_sizes, int n_in,
                              void* d_out, int out_size) {
    const int*   x   = (const int*)  d_in[0];
    const float* emb = (const float*)d_in[1];
    const float* Wg  = (const float*)d_in[2];
    const float* bg  = (const float*)d_in[3];
    const float* Wh  = (const float*)d_in[4];
    const float* bh  = (const float*)d_in[5];
    const float* Wo  = (const float*)d_in[6];
    const float* bo  = (const float*)d_in[7];
    float* out = (float*)d_out;

    float *pEmbW, *pEmbR, *pWxT, *pWoT, *pHs;
    cudaGetSymbolAddress((void**)&pEmbW, g_EmbW);
    cudaGetSymbolAddress((void**)&pEmbR, g_embR);
    cudaGetSymbolAddress((void**)&pWxT,  g_WxT);
    cudaGetSymbolAddress((void**)&pWoT,  g_WoT);
    cudaGetSymbolAddress((void**)&pHs,   g_Hs);

    cudaFuncSetAttribute(gru_persistent,
                         cudaFuncAttributeMaxDynamicSharedMemorySize, SMEM_BYTES);

    pack_weights<<<7168, 256>>>(Wg, Wh, Wo);
    round_emb<<<(Vn * Hn + 255) / 256, 256>>>(emb);
    gemm_db<<<dim3(N1 / 128, (Vn + 127) / 128), 256>>>(pEmbR, pWxT, pEmbW, nullptr,
                                                       Vn, N1, Hn);
    zero_misc<<<(Bn * Hn + 255) / 256, 256>>>();
    gru_persistent<<<128, 256, SMEM_BYTES>>>(x, bg, bh);
    gemm_db<<<dim3(On / 128, (Bn * Sn) / 128), 256>>>(pHs, pWoT, out + Bn * Hn, bo,
                                                      Bn * Sn, On, Hn);
    copy_h<<<(Bn * Hn + 255) / 256, 256>>>(out);
}

// round 9
// speedup vs baseline: 1.3423x; 1.0283x over previous
#include <cuda_runtime.h>
#include <math.h>
#include <stdint.h>

#define Vn 10000
#define Hn 512
#define On 512
#define Bn 256
#define Sn 256
#define N1 1536

#define NJ 16
#define NG 8
#define RB 32
#define PAD_ST 132
// smem: sWgz[512*64] + sWh[512*32] + sSt[32*132] + zbuf[32*33] + hbuf[32*33]
#define SMEM_BYTES ((512*64 + 512*32 + 32*PAD_ST + 2*32*33) * 4)

// ---------------- scratch ----------------------------------------------------
__device__ float g_EmbW[(size_t)Vn * N1];
__device__ float g_embR[(size_t)Vn * Hn];      // tf32-rounded emb
__device__ float g_WxT [Hn * N1];              // tf32-rounded
__device__ float g_WgHt[Hn * 1024];
__device__ float g_WhHt[Hn * Hn];
__device__ float g_WoT [Hn * On];              // tf32-rounded
__device__ float g_hR  [Bn * Hn];              // rounded h (A-operand exchange)
__device__ float g_rh  [Bn * Hn];              // rounded r*h
__device__ float g_Hs  [(size_t)Bn * Sn * Hn]; // rounded hidden states
__device__ __align__(64) int g_flag1[NG][16];  // phase1 completion per CTA
__device__ __align__(64) int g_flag2[NG][16];  // phase2 completion per CTA

// ---------------- helpers ----------------------------------------------------
__device__ __forceinline__ float f2tff(float f) {
    uint32_t u; asm("cvt.rna.tf32.f32 %0, %1;" : "=r"(u) : "f"(f));
    return __uint_as_float(u);
}
#define MMA_TF32(C, a0,a1,a2,a3, b0,b1)                                        \
    asm volatile("mma.sync.aligned.m16n8k8.row.col.f32.tf32.tf32.f32 "         \
                 "{%0,%1,%2,%3}, {%4,%5,%6,%7}, {%8,%9}, {%0,%1,%2,%3};"       \
                 : "+f"((C)[0]), "+f"((C)[1]), "+f"((C)[2]), "+f"((C)[3])      \
                 : "r"(a0), "r"(a1), "r"(a2), "r"(a3), "r"(b0), "r"(b1))

__device__ __forceinline__ uint32_t s2u(const void* p) {
    return (uint32_t)__cvta_generic_to_shared(p);
}
__device__ __forceinline__ void cp16(uint32_t dst, const void* src, bool pred) {
    int sz = pred ? 16 : 0;
    asm volatile("cp.async.cg.shared.global [%0], [%1], 16, %2;"
                 :: "r"(dst), "l"(src), "r"(sz) : "memory");
}
#define CP_COMMIT() asm volatile("cp.async.commit_group;" ::: "memory")
#define CP_WAIT1()  asm volatile("cp.async.wait_group 1;" ::: "memory")

// -------- sync primitives ----------------------------------------------------
__device__ __forceinline__ int ld_acq(const int* p) {
    int v; asm volatile("ld.acquire.gpu.global.s32 %0, [%1];" : "=r"(v) : "l"(p) : "memory");
    return v;
}
__device__ __forceinline__ void wait4(const int* f, int target) {
    while (ld_acq(f + 0) < target) {}
    while (ld_acq(f + 1) < target) {}
    while (ld_acq(f + 2) < target) {}
    while (ld_acq(f + 3) < target) {}
}
__device__ __forceinline__ void flag_store(int* f, int v) {
    __threadfence();
    atomicExch(f, v);
}
// named barriers: 1..8 = pass gates, 9 = worker barrier, 10 = step handshake
#define BARW()        asm volatile("bar.sync 9, 256;" ::: "memory")
#define GATE_SYNC(id) asm volatile("bar.sync %0, 288;" :: "r"(id) : "memory")
#define GATE_ARR(id)  asm volatile("bar.arrive %0, 288;" :: "r"(id) : "memory")
#define STEP_ARR()    asm volatile("bar.arrive 10, 288;" ::: "memory")
#define STEP_SYNC()   asm volatile("bar.sync 10, 288;" ::: "memory")

// ---------------- weight packing ---------------------------------------------
__global__ void pack_weights(const float* __restrict__ Wg,
                             const float* __restrict__ Wh,
                             const float* __restrict__ Wo) {
    int idx = blockIdx.x * blockDim.x + threadIdx.x;
    const int s1 = Hn * N1, s2 = Hn * 1024, s3 = Hn * Hn, s4 = Hn * On;
    if (idx < s1) {
        int k = idx / N1, n = idx % N1;
        g_WxT[idx] = f2tff((n < 1024) ? Wg[n * 1024 + k] : Wh[(n - 1024) * 1024 + k]);
    } else if (idx < s1 + s2) {
        int r = idx - s1; int k = r / 1024, j = r % 1024;
        g_WgHt[r] = Wg[j * 1024 + 512 + k];
    } else if (idx < s1 + s2 + s3) {
        int r = idx - s1 - s2; int k = r / 512, j = r % 512;
        g_WhHt[r] = Wh[j * 1024 + 512 + k];
    } else if (idx < s1 + s2 + s3 + s4) {
        int r = idx - s1 - s2 - s3; int k = r / 512, o = r % 512;
        g_WoT[r] = f2tff(Wo[o * 512 + k]);
    }
}

// round emb + zero state/flags (merged so gru lands at profiled launch slot)
__global__ void round_zero(const float* __restrict__ emb) {
    int i = blockIdx.x * blockDim.x + threadIdx.x;
    if (i < Vn * Hn) g_embR[i] = f2tff(emb[i]);
    if (i < Bn * Hn) g_hR[i] = 0.f;
    if (i < NG * 16) { g_flag1[i >> 4][i & 15] = 0; g_flag2[i >> 4][i & 15] = 0; }
}

// ------- double-buffered tf32 GEMM: C[M,N] = A[M,K] @ Bt[K,N] (+bias) -------
__global__ void __launch_bounds__(256)
gemm_db(const float* __restrict__ A, const float* __restrict__ Bt,
        float* __restrict__ C, const float* __restrict__ bias,
        int M, int N, int K) {
    __shared__ float As[2][128 * 20];
    __shared__ float Bs[2][16 * 136];
    const int tid = threadIdx.x, w = tid >> 5, l = tid & 31;
    const int wm = w >> 2, wn = w & 3;
    const int mBase = blockIdx.y * 128, nBase = blockIdx.x * 128;

    const int ar = tid >> 1, ac = (tid & 1) * 8;
    const int br = tid >> 4, bc = (tid & 15) * 4;

    auto stage = [&](int s, int k0) {
        bool pA = (mBase + ar) < M;
        const float* srcA = &A[(size_t)(mBase + ar) * K + k0 + ac];
        cp16(s2u(&As[s][ar * 20 + ac]),     srcA,     pA);
        cp16(s2u(&As[s][ar * 20 + ac + 4]), srcA + 4, pA);
        const float* srcB = &Bt[(size_t)(k0 + br) * N + nBase + bc];
        cp16(s2u(&Bs[s][br * 136 + bc]),      srcB,      true);
        cp16(s2u(&Bs[s][br * 136 + bc + 64]), srcB + 64, true);
    };

    float acc[4][4][4] = {};
    const int nIter = K / 16;
    stage(0, 0); CP_COMMIT();
    for (int it = 0; it < nIter; it++) {
        if (it + 1 < nIter) stage((it + 1) & 1, (it + 1) * 16);
        CP_COMMIT();
        CP_WAIT1();
        __syncthreads();
        const float* as = As[it & 1];
        const float* bs = Bs[it & 1];
        #pragma unroll
        for (int ks = 0; ks < 2; ks++) {
            const int kk = ks * 8 + (l & 3);
            uint32_t bfr[4][2];
            #pragma unroll
            for (int nt = 0; nt < 4; nt++) {
                int n = wn * 32 + nt * 8 + (l >> 2);
                bfr[nt][0] = __float_as_uint(bs[kk * 136 + n]);
                bfr[nt][1] = __float_as_uint(bs[(kk + 4) * 136 + n]);
            }
            #pragma unroll
            for (int mt = 0; mt < 4; mt++) {
                int r = wm * 64 + mt * 16 + (l >> 2);
                uint32_t a0 = __float_as_uint(as[r * 20 + kk]);
                uint32_t a1 = __float_as_uint(as[(r + 8) * 20 + kk]);
                uint32_t a2 = __float_as_uint(as[r * 20 + kk + 4]);
                uint32_t a3 = __float_as_uint(as[(r + 8) * 20 + kk + 4]);
                #pragma unroll
                for (int nt = 0; nt < 4; nt++)
                    MMA_TF32(acc[mt][nt], a0, a1, a2, a3, bfr[nt][0], bfr[nt][1]);
            }
        }
        __syncthreads();
    }
    #pragma unroll
    for (int mt = 0; mt < 4; mt++) {
        #pragma unroll
        for (int nt = 0; nt < 4; nt++) {
            #pragma unroll
            for (int rr = 0; rr < 4; rr++) {
                int row = mBase + wm * 64 + mt * 16 + (l >> 2) + ((rr >= 2) ? 8 : 0);
                if (row >= M) continue;
                int col = nBase + wn * 32 + nt * 8 + (l & 3) * 2 + (rr & 1);
                float v = acc[mt][nt][rr];
                if (bias) v += bias[col];
                C[(size_t)row * N + col] = v;
            }
        }
    }
}

// ------- persistent GRU recurrence: 8 worker warps + 1 sync warp -------------
__global__ void __launch_bounds__(288, 1)
gru_persistent(const int* __restrict__ x, const float* __restrict__ bg,
               const float* __restrict__ bh, float* __restrict__ hOut) {
    extern __shared__ float sm[];
    float* sWgz = sm;                           // [512][64]: n<32 r-cols, n>=32 z-cols
    float* sWh  = sWgz + 512 * 64;              // [512][32]
    float* sSt  = sWh + 512 * 32;               // [32][PAD_ST]
    float* zbuf = sSt + 32 * PAD_ST;            // [32][33]
    float* hbuf = zbuf + 32 * 33;               // [32][33]

    const int jt  = blockIdx.x & 15;
    const int g   = blockIdx.x >> 4;
    const int tid = threadIdx.x;
    const int bBase = g * RB;

    // all 288 threads help load weights
    for (int i = tid; i < 512 * 64; i += 288) {
        int k = i >> 6, c = i & 63;
        int gcol = (c < 32) ? (512 + jt * 32 + c) : (jt * 32 + c - 32);
        sWgz[k * 64 + (c ^ ((k & 3) * 8))] = f2tff(g_WgHt[k * 1024 + gcol]);
    }
    for (int i = tid; i < 512 * 32; i += 288) {
        int k = i >> 5, c = i & 31;
        sWh[k * 32 + (c ^ ((k & 3) * 8))] = f2tff(g_WhHt[k * 512 + jt * 32 + c]);
    }
    for (int i = tid; i < 32 * 33; i += 288) { zbuf[i] = 0.f; hbuf[i] = 0.f; }
    __syncthreads();

    // ================= sync warp =================
    if (tid >= 256) {
        for (int t = 0; t < Sn; t++) {
            #pragma unroll
            for (int p = 0; p < 4; p++) {
                if ((tid & 31) == 0) wait4(&g_flag2[g][4 * p], t);
                __syncwarp(0xFFFFFFFFu);
                GATE_ARR(1 + p);
            }
            #pragma unroll
            for (int p = 0; p < 4; p++) {
                if ((tid & 31) == 0) wait4(&g_flag1[g][4 * p], t + 1);
                __syncwarp(0xFFFFFFFFu);
                GATE_ARR(5 + p);
            }
            STEP_SYNC();   // bound: <=1 step ahead of workers
        }
        return;
    }

    // ================= worker warps =================
    const int w  = tid >> 5, l = tid & 31;
    const int mt = w & 1;
    const int wn = w >> 1;
    const int row0 = bBase + mt * 16 + (l >> 2);

    float bgv[4], bhv[2];
    #pragma unroll
    for (int ti = 0; ti < 2; ti++)
        #pragma unroll
        for (int p = 0; p < 2; p++) {
            int n = wn * 16 + ti * 8 + (l & 3) * 2 + p;
            int gcol = (n < 32) ? (512 + jt * 32 + n) : (jt * 32 + n - 32);
            bgv[ti * 2 + p] = bg[gcol];
        }
    #pragma unroll
    for (int p = 0; p < 2; p++)
        bhv[p] = bh[jt * 32 + wn * 8 + (l & 3) * 2 + p];

    int srow[4], skq[4];
    #pragma unroll
    for (int j = 0; j < 4; j++) {
        int i = tid + j * 256;
        srow[j] = i >> 5; skq[j] = (i & 31) * 4;
    }

    float hreg[4] = {0.f, 0.f, 0.f, 0.f};

    for (int t = 0; t < Sn; t++) {
        const int tok0 = __ldg(&x[row0 * Sn + t]);
        const int tok1 = __ldg(&x[(row0 + 8) * Sn + t]);

        float ew1[8], hv1[8], ew2[4];
        #pragma unroll
        for (int ti = 0; ti < 2; ti++)
            #pragma unroll
            for (int rr = 0; rr < 4; rr++) {
                int tok = (rr < 2) ? tok0 : tok1;
                int n = wn * 16 + ti * 8 + (l & 3) * 2 + (rr & 1);
                int gcol = (n < 32) ? (512 + jt * 32 + n) : (jt * 32 + n - 32);
                ew1[ti * 4 + rr] = __ldg(&g_EmbW[(size_t)tok * N1 + gcol]);
                int rl = mt * 16 + (l >> 2) + ((rr >= 2) ? 8 : 0);
                hv1[ti * 4 + rr] = hbuf[rl * 33 + (n & 31)];
            }
        #pragma unroll
        for (int rr = 0; rr < 4; rr++) {
            int tok = (rr < 2) ? tok0 : tok1;
            int n2 = wn * 8 + (l & 3) * 2 + (rr & 1);
            ew2[rr] = __ldg(&g_EmbW[(size_t)tok * N1 + 1024 + jt * 32 + n2]);
        }

        // ===== phase 1: (r|z) = h @ sWgz; gates 1..4, A = g_hR =====
        float acc[8] = {};
        {
            float4 pf[4];
            GATE_SYNC(1);
            #pragma unroll
            for (int j = 0; j < 4; j++)
                pf[j] = __ldcg((const float4*)&g_hR[(bBase + srow[j]) * 512 + skq[j]]);
            #pragma unroll
            for (int j = 0; j < 4; j++)
                *(float4*)&sSt[srow[j] * PAD_ST + skq[j]] = pf[j];
            for (int pass = 0; pass < 4; pass++) {
                const int kb = pass * 128;
                if (pass < 3) {
                    int gid = 2 + pass;
                    GATE_SYNC(gid);
                    #pragma unroll
                    for (int j = 0; j < 4; j++)
                        pf[j] = __ldcg((const float4*)&g_hR[(bBase + srow[j]) * 512
                                                            + kb + 128 + skq[j]]);
                }
                BARW();
                #pragma unroll
                for (int ks = 0; ks < 16; ks++) {
                    const float* ap = &sSt[(mt * 16 + (l >> 2)) * PAD_ST + ks * 8 + (l & 3)];
                    uint32_t a0 = __float_as_uint(ap[0]);
                    uint32_t a1 = __float_as_uint(ap[8 * PAD_ST]);
                    uint32_t a2 = __float_as_uint(ap[4]);
                    uint32_t a3 = __float_as_uint(ap[8 * PAD_ST + 4]);
                    const int kg = kb + ks * 8 + (l & 3);
                    const int sw = (kg & 3) * 8;
                    #pragma unroll
                    for (int ti = 0; ti < 2; ti++) {
                        int n = (wn * 16 + ti * 8 + (l >> 2)) ^ sw;
                        uint32_t b0 = __float_as_uint(sWgz[kg * 64 + n]);
                        uint32_t b1 = __float_as_uint(sWgz[(kg + 4) * 64 + n]);
                        MMA_TF32(acc + ti * 4, a0, a1, a2, a3, b0, b1);
                    }
                }
                if (pass < 3) {
                    BARW();
                    #pragma unroll
                    for (int j = 0; j < 4; j++)
                        *(float4*)&sSt[srow[j] * PAD_ST + skq[j]] = pf[j];
                }
            }
        }
        #pragma unroll
        for (int ti = 0; ti < 2; ti++) {
            #pragma unroll
            for (int rr = 0; rr < 4; rr++) {
                int row = (rr < 2) ? row0 : (row0 + 8);
                int rl  = mt * 16 + (l >> 2) + ((rr >= 2) ? 8 : 0);
                int n = wn * 16 + ti * 8 + (l & 3) * 2 + (rr & 1);
                float gv = acc[ti * 4 + rr] + ew1[ti * 4 + rr] + bgv[ti * 2 + (rr & 1)];
                float s = 1.f / (1.f + __expf(-gv));
                if (n < 32) {
                    __stcg(&g_rh[row * 512 + jt * 32 + n], f2tff(s * hv1[ti * 4 + rr]));
                } else {
                    zbuf[rl * 33 + (n - 32)] = s;
                }
            }
        }
        BARW();
        if (tid == 0) flag_store(&g_flag1[g][jt], t + 1);

        // ===== phase 2: cand = rh @ sWh; gates 5..8, A = g_rh =====
        float acc2[4] = {};
        {
            float4 pf[4];
            GATE_SYNC(5);
            #pragma unroll
            for (int j = 0; j < 4; j++)
                pf[j] = __ldcg((const float4*)&g_rh[(bBase + srow[j]) * 512 + skq[j]]);
            #pragma unroll
            for (int j = 0; j < 4; j++)
                *(float4*)&sSt[srow[j] * PAD_ST + skq[j]] = pf[j];
            for (int pass = 0; pass < 4; pass++) {
                const int kb = pass * 128;
                if (pass < 3) {
                    int gid = 6 + pass;
                    GATE_SYNC(gid);
                    #pragma unroll
                    for (int j = 0; j < 4; j++)
                        pf[j] = __ldcg((const float4*)&g_rh[(bBase + srow[j]) * 512
                                                            + kb + 128 + skq[j]]);
                }
                BARW();
                #pragma unroll
                for (int ks = 0; ks < 16; ks++) {
                    const float* ap = &sSt[(mt * 16 + (l >> 2)) * PAD_ST + ks * 8 + (l & 3)];
                    uint32_t a0 = __float_as_uint(ap[0]);
                    uint32_t a1 = __float_as_uint(ap[8 * PAD_ST]);
                    uint32_t a2 = __float_as_uint(ap[4]);
                    uint32_t a3 = __float_as_uint(ap[8 * PAD_ST + 4]);
                    const int kg = kb + ks * 8 + (l & 3);
                    const int sw = (kg & 3) * 8;
                    int n = (wn * 8 + (l >> 2)) ^ sw;
                    uint32_t b0 = __float_as_uint(sWh[kg * 32 + n]);
                    uint32_t b1 = __float_as_uint(sWh[(kg + 4) * 32 + n]);
                    MMA_TF32(acc2, a0, a1, a2, a3, b0, b1);
                }
                if (pass < 3) {
                    BARW();
                    #pragma unroll
                    for (int j = 0; j < 4; j++)
                        *(float4*)&sSt[srow[j] * PAD_ST + skq[j]] = pf[j];
                }
            }
        }
        #pragma unroll
        for (int rr = 0; rr < 4; rr++) {
            int row = (rr < 2) ? row0 : (row0 + 8);
            int rl  = mt * 16 + (l >> 2) + ((rr >= 2) ? 8 : 0);
            int n2  = wn * 8 + (l & 3) * 2 + (rr & 1);
            int col = jt * 32 + n2;
            float cand = tanhf(acc2[rr] + ew2[rr] + bhv[rr & 1]);
            float zz = zbuf[rl * 33 + n2];
            float hn = fmaf(zz, cand - hreg[rr], hreg[rr]);
            hreg[rr] = hn;
            hbuf[rl * 33 + n2] = hn;
            float hr = f2tff(hn);
            __stcg(&g_hR[row * 512 + col], hr);
            __stcg(&g_Hs[((size_t)row * Sn + t) * 512 + col], hr);
            if (t == Sn - 1) hOut[row * 512 + col] = hn;
        }
        BARW();
        if (tid == 0) flag_store(&g_flag2[g][jt], t + 1);
        STEP_ARR();
    }
}

// ---------------- entry ------------------------------------------------------
extern "C" void kernel_launch(void* const* d_in, const int* in_sizes, int n_in,
                              void* d_out, int out_size) {
    const int*   x   = (const int*)  d_in[0];
    const float* emb = (const float*)d_in[1];
    const float* Wg  = (const float*)d_in[2];
    const float* bg  = (const float*)d_in[3];
    const float* Wh  = (const float*)d_in[4];
    const float* bh  = (const float*)d_in[5];
    const float* Wo  = (const float*)d_in[6];
    const float* bo  = (const float*)d_in[7];
    float* out = (float*)d_out;

    float *pEmbW, *pEmbR, *pWxT, *pWoT, *pHs;
    cudaGetSymbolAddress((void**)&pEmbW, g_EmbW);
    cudaGetSymbolAddress((void**)&pEmbR, g_embR);
    cudaGetSymbolAddress((void**)&pWxT,  g_WxT);
    cudaGetSymbolAddress((void**)&pWoT,  g_WoT);
    cudaGetSymbolAddress((void**)&pHs,   g_Hs);

    cudaFuncSetAttribute(gru_persistent,
                         cudaFuncAttributeMaxDynamicSharedMemorySize, SMEM_BYTES);

    pack_weights<<<7168, 256>>>(Wg, Wh, Wo);
    round_zero<<<(Vn * Hn + 255) / 256, 256>>>(emb);
    gemm_db<<<dim3(N1 / 128, (Vn + 127) / 128), 256>>>(pEmbR, pWxT, pEmbW, nullptr,
                                                       Vn, N1, Hn);
    gru_persistent<<<128, 288, SMEM_BYTES>>>(x, bg, bh, out);
    gemm_db<<<dim3(On / 128, (Bn * Sn) / 128), 256>>>(pHs, pWoT, out + Bn * Hn, bo,
                                                      Bn * Sn, On, Hn);
}

// round 10
// speedup vs baseline: 1.6239x; 1.2098x over previous
#include <cuda_runtime.h>
#include <math.h>
#include <stdint.h>

#define Vn 10000
#define Hn 512
#define On 512
#define Bn 256
#define Sn 256
#define N1 1536

#define NJ 16
#define NG 8
#define RB 32
// smem: sWgz[512*64] + sWh[512*32] + 2 x sSt[32*128] (XOR-swizzled)
#define SMEM_BYTES ((512*64 + 512*32 + 2*32*128) * 4)

// ---------------- scratch ----------------------------------------------------
__device__ float g_EmbW[(size_t)Vn * N1];
__device__ float g_embR[(size_t)Vn * Hn];      // tf32-rounded emb
__device__ float g_WxT [Hn * N1];              // tf32-rounded
__device__ float g_WgHt[Hn * 1024];
__device__ float g_WhHt[Hn * Hn];
__device__ float g_WoT [Hn * On];              // tf32-rounded
__device__ float g_hR  [Bn * Hn];              // rounded h (cross-CTA A operand)
__device__ float g_rh  [Bn * Hn];              // rounded r*h (cross-CTA)
__device__ float g_Hs  [(size_t)Bn * Sn * Hn]; // rounded hidden states
__device__ float g_zOwn[128 * RB * 32];        // CTA-private z (exact)
__device__ float g_hOwn[128 * RB * 32];        // CTA-private h (exact)
__device__ int   g_ctr [NG];

// ---------------- helpers ----------------------------------------------------
__device__ __forceinline__ float f2tff(float f) {
    uint32_t u; asm("cvt.rna.tf32.f32 %0, %1;" : "=r"(u) : "f"(f));
    return __uint_as_float(u);
}
#define MMA_TF32(C, a0,a1,a2,a3, b0,b1)                                        \
    asm volatile("mma.sync.aligned.m16n8k8.row.col.f32.tf32.tf32.f32 "         \
                 "{%0,%1,%2,%3}, {%4,%5,%6,%7}, {%8,%9}, {%0,%1,%2,%3};"       \
                 : "+f"((C)[0]), "+f"((C)[1]), "+f"((C)[2]), "+f"((C)[3])      \
                 : "r"(a0), "r"(a1), "r"(a2), "r"(a3), "r"(b0), "r"(b1))

__device__ __forceinline__ uint32_t s2u(const void* p) {
    return (uint32_t)__cvta_generic_to_shared(p);
}
__device__ __forceinline__ void cp16(uint32_t dst, const void* src, bool pred) {
    int sz = pred ? 16 : 0;
    asm volatile("cp.async.cg.shared.global [%0], [%1], 16, %2;"
                 :: "r"(dst), "l"(src), "r"(sz) : "memory");
}
#define CP_COMMIT() asm volatile("cp.async.commit_group;" ::: "memory")
#define CP_WAIT1()  asm volatile("cp.async.wait_group 1;" ::: "memory")

__device__ __forceinline__ int ld_acq(const int* p) {
    int v; asm volatile("ld.acquire.gpu.global.s32 %0, [%1];" : "=r"(v) : "l"(p) : "memory");
    return v;
}

// ---------------- weight packing ---------------------------------------------
__global__ void pack_weights(const float* __restrict__ Wg,
                             const float* __restrict__ Wh,
                             const float* __restrict__ Wo) {
    int idx = blockIdx.x * blockDim.x + threadIdx.x;
    const int s1 = Hn * N1, s2 = Hn * 1024, s3 = Hn * Hn, s4 = Hn * On;
    if (idx < s1) {
        int k = idx / N1, n = idx % N1;
        g_WxT[idx] = f2tff((n < 1024) ? Wg[n * 1024 + k] : Wh[(n - 1024) * 1024 + k]);
    } else if (idx < s1 + s2) {
        int r = idx - s1; int k = r / 1024, j = r % 1024;
        g_WgHt[r] = Wg[j * 1024 + 512 + k];
    } else if (idx < s1 + s2 + s3) {
        int r = idx - s1 - s2; int k = r / 512, j = r % 512;
        g_WhHt[r] = Wh[j * 1024 + 512 + k];
    } else if (idx < s1 + s2 + s3 + s4) {
        int r = idx - s1 - s2 - s3; int k = r / 512, o = r % 512;
        g_WoT[r] = f2tff(Wo[o * 512 + k]);
    }
}

// round emb + zero state/flags
__global__ void round_zero(const float* __restrict__ emb) {
    int i = blockIdx.x * blockDim.x + threadIdx.x;
    if (i < Vn * Hn) g_embR[i] = f2tff(emb[i]);
    if (i < Bn * Hn) g_hR[i] = 0.f;
    if (i < 128 * RB * 32) g_hOwn[i] = 0.f;
    if (i < NG) g_ctr[i] = 0;
}

// ------- double-buffered tf32 GEMM: C[M,N] = A[M,K] @ Bt[K,N] (+bias) -------
__global__ void __launch_bounds__(256)
gemm_db(const float* __restrict__ A, const float* __restrict__ Bt,
        float* __restrict__ C, const float* __restrict__ bias,
        int M, int N, int K) {
    __shared__ float As[2][128 * 20];
    __shared__ float Bs[2][16 * 136];
    const int tid = threadIdx.x, w = tid >> 5, l = tid & 31;
    const int wm = w >> 2, wn = w & 3;
    const int mBase = blockIdx.y * 128, nBase = blockIdx.x * 128;

    const int ar = tid >> 1, ac = (tid & 1) * 8;
    const int br = tid >> 4, bc = (tid & 15) * 4;

    auto stage = [&](int s, int k0) {
        bool pA = (mBase + ar) < M;
        const float* srcA = &A[(size_t)(mBase + ar) * K + k0 + ac];
        cp16(s2u(&As[s][ar * 20 + ac]),     srcA,     pA);
        cp16(s2u(&As[s][ar * 20 + ac + 4]), srcA + 4, pA);
        const float* srcB = &Bt[(size_t)(k0 + br) * N + nBase + bc];
        cp16(s2u(&Bs[s][br * 136 + bc]),      srcB,      true);
        cp16(s2u(&Bs[s][br * 136 + bc + 64]), srcB + 64, true);
    };

    float acc[4][4][4] = {};
    const int nIter = K / 16;
    stage(0, 0); CP_COMMIT();
    for (int it = 0; it < nIter; it++) {
        if (it + 1 < nIter) stage((it + 1) & 1, (it + 1) * 16);
        CP_COMMIT();
        CP_WAIT1();
        __syncthreads();
        const float* as = As[it & 1];
        const float* bs = Bs[it & 1];
        #pragma unroll
        for (int ks = 0; ks < 2; ks++) {
            const int kk = ks * 8 + (l & 3);
            uint32_t bfr[4][2];
            #pragma unroll
            for (int nt = 0; nt < 4; nt++) {
                int n = wn * 32 + nt * 8 + (l >> 2);
                bfr[nt][0] = __float_as_uint(bs[kk * 136 + n]);
                bfr[nt][1] = __float_as_uint(bs[(kk + 4) * 136 + n]);
            }
            #pragma unroll
            for (int mt = 0; mt < 4; mt++) {
                int r = wm * 64 + mt * 16 + (l >> 2);
                uint32_t a0 = __float_as_uint(as[r * 20 + kk]);
                uint32_t a1 = __float_as_uint(as[(r + 8) * 20 + kk]);
                uint32_t a2 = __float_as_uint(as[r * 20 + kk + 4]);
                uint32_t a3 = __float_as_uint(as[(r + 8) * 20 + kk + 4]);
                #pragma unroll
                for (int nt = 0; nt < 4; nt++)
                    MMA_TF32(acc[mt][nt], a0, a1, a2, a3, bfr[nt][0], bfr[nt][1]);
            }
        }
        __syncthreads();
    }
    #pragma unroll
    for (int mt = 0; mt < 4; mt++) {
        #pragma unroll
        for (int nt = 0; nt < 4; nt++) {
            #pragma unroll
            for (int rr = 0; rr < 4; rr++) {
                int row = mBase + wm * 64 + mt * 16 + (l >> 2) + ((rr >= 2) ? 8 : 0);
                if (row >= M) continue;
                int col = nBase + wn * 32 + nt * 8 + (l & 3) * 2 + (rr & 1);
                float v = acc[mt][nt][rr];
                if (bias) v += bias[col];
                C[(size_t)row * N + col] = v;
            }
        }
    }
}

// ------- persistent GRU: R5 pipeline + symmetric repartition -----------------
__global__ void __launch_bounds__(256, 1)
gru_persistent(const int* __restrict__ x, const float* __restrict__ bg,
               const float* __restrict__ bh, float* __restrict__ hOut) {
    extern __shared__ float sm[];
    float* sWgz = sm;                           // [512][64]: n<32 r-cols, n>=32 z-cols
    float* sWh  = sWgz + 512 * 64;              // [512][32]
    float* sSt0 = sWh + 512 * 32;               // [32][128] XOR-swizzled
    float* sSt1 = sSt0 + 32 * 128;

    const int jt  = blockIdx.x & 15;
    const int g   = blockIdx.x >> 4;
    const int tid = threadIdx.x;
    const int w   = tid >> 5, l = tid & 31;
    const int mt  = w & 1;
    const int wn  = w >> 1;
    const int bBase = g * RB;

    float* zOwn = g_zOwn + blockIdx.x * (RB * 32);  // [32][32] CTA-private
    float* hOwn = g_hOwn + blockIdx.x * (RB * 32);

    // weights, XOR-swizzled (proven layout)
    for (int i = tid; i < 512 * 64; i += 256) {
        int k = i >> 6, c = i & 63;
        int gcol = (c < 32) ? (512 + jt * 32 + c) : (jt * 32 + c - 32);
        sWgz[k * 64 + (c ^ ((k & 3) * 8))] = f2tff(g_WgHt[k * 1024 + gcol]);
    }
    for (int i = tid; i < 512 * 32; i += 256) {
        int k = i >> 5, c = i & 31;
        sWh[k * 32 + (c ^ ((k & 3) * 8))] = f2tff(g_WhHt[k * 512 + jt * 32 + c]);
    }
    __syncthreads();

    const int row0 = bBase + mt * 16 + (l >> 2);
    float bgv[4], bhv[2];
    #pragma unroll
    for (int ti = 0; ti < 2; ti++)
        #pragma unroll
        for (int p = 0; p < 2; p++) {
            int n = wn * 16 + ti * 8 + (l & 3) * 2 + p;
            int gcol = (n < 32) ? (512 + jt * 32 + n) : (jt * 32 + n - 32);
            bgv[ti * 2 + p] = bg[gcol];
        }
    #pragma unroll
    for (int p = 0; p < 2; p++)
        bhv[p] = bh[jt * 32 + wn * 8 + (l & 3) * 2 + p];

    // staging indices: 32 rows x 128 cols per pass, 4 float4/thread
    int srow[4], sptr[4], gofs[4];
    #pragma unroll
    for (int j = 0; j < 4; j++) {
        int i = tid + j * 256;
        srow[j] = i >> 5;
        int kq  = (i & 31) * 4;
        sptr[j] = srow[j] * 128 + (kq ^ (4 * (srow[j] & 7)));
        gofs[j] = (bBase + srow[j]) * 512 + kq;
    }
    const int arow = mt * 16 + (l >> 2);
    const int xr   = 4 * ((l >> 2) & 7);    // a-frag XOR (row&7 == l>>2)

    float hreg[4] = {0.f, 0.f, 0.f, 0.f};
    int target = 0;

    for (int t = 0; t < Sn; t++) {
        const int tok0 = __ldg(&x[row0 * Sn + t]);
        const int tok1 = __ldg(&x[(row0 + 8) * Sn + t]);

        // prefetch epilogue operands
        float ew1[8], hv1[8], ew2[4];
        #pragma unroll
        for (int ti = 0; ti < 2; ti++)
            #pragma unroll
            for (int rr = 0; rr < 4; rr++) {
                int tok = (rr < 2) ? tok0 : tok1;
                int n = wn * 16 + ti * 8 + (l & 3) * 2 + (rr & 1);
                int gcol = (n < 32) ? (512 + jt * 32 + n) : (jt * 32 + n - 32);
                ew1[ti * 4 + rr] = __ldg(&g_EmbW[(size_t)tok * N1 + gcol]);
                int rl = mt * 16 + (l >> 2) + ((rr >= 2) ? 8 : 0);
                hv1[ti * 4 + rr] = hOwn[rl * 32 + (n & 31)];
            }
        #pragma unroll
        for (int rr = 0; rr < 4; rr++) {
            int tok = (rr < 2) ? tok0 : tok1;
            int n2 = wn * 8 + (l & 3) * 2 + (rr & 1);
            ew2[rr] = __ldg(&g_EmbW[(size_t)tok * N1 + 1024 + jt * 32 + n2]);
        }

        // ===== phase 1: (r|z) = h @ sWgz =====
        float acc[8] = {};
        {
            float4 pf[4];
            #pragma unroll
            for (int j = 0; j < 4; j++)
                pf[j] = __ldcg((const float4*)&g_hR[gofs[j]]);
            #pragma unroll
            for (int j = 0; j < 4; j++)
                *(float4*)&sSt0[sptr[j]] = pf[j];   // pre-rounded
            for (int pass = 0; pass < 4; pass++) {
                const int kb = pass * 128;
                if (pass < 3) {
                    #pragma unroll
                    for (int j = 0; j < 4; j++)
                        pf[j] = __ldcg((const float4*)&g_hR[gofs[j] + kb + 128]);
                }
                __syncthreads();
                const float* st = (pass & 1) ? sSt1 : sSt0;
                #pragma unroll
                for (int ks = 0; ks < 16; ks++) {
                    int c0 = (ks * 8 + (l & 3)) ^ xr;
                    int c1 = (ks * 8 + (l & 3) + 4) ^ xr;
                    uint32_t a0 = __float_as_uint(st[arow * 128 + c0]);
                    uint32_t a1 = __float_as_uint(st[(arow + 8) * 128 + c0]);
                    uint32_t a2 = __float_as_uint(st[arow * 128 + c1]);
                    uint32_t a3 = __float_as_uint(st[(arow + 8) * 128 + c1]);
                    const int kg = kb + ks * 8 + (l & 3);
                    const int sw = (kg & 3) * 8;
                    #pragma unroll
                    for (int ti = 0; ti < 2; ti++) {
                        int n = (wn * 16 + ti * 8 + (l >> 2)) ^ sw;
                        uint32_t b0 = __float_as_uint(sWgz[kg * 64 + n]);
                        uint32_t b1 = __float_as_uint(sWgz[(kg + 4) * 64 + n]);
                        MMA_TF32(acc + ti * 4, a0, a1, a2, a3, b0, b1);
                    }
                }
                if (pass < 3) {
                    float* dst = (pass & 1) ? sSt0 : sSt1;
                    #pragma unroll
                    for (int j = 0; j < 4; j++)
                        *(float4*)&dst[sptr[j]] = pf[j];
                }
            }
        }
        #pragma unroll
        for (int ti = 0; ti < 2; ti++) {
            #pragma unroll
            for (int rr = 0; rr < 4; rr++) {
                int row = (rr < 2) ? row0 : (row0 + 8);
                int rl  = mt * 16 + (l >> 2) + ((rr >= 2) ? 8 : 0);
                int n = wn * 16 + ti * 8 + (l & 3) * 2 + (rr & 1);
                float gv = acc[ti * 4 + rr] + ew1[ti * 4 + rr] + bgv[ti * 2 + (rr & 1)];
                float s = 1.f / (1.f + __expf(-gv));
                if (n < 32) {
                    __stcg(&g_rh[row * 512 + jt * 32 + n], f2tff(s * hv1[ti * 4 + rr]));
                } else {
                    zOwn[rl * 32 + (n - 32)] = s;
                }
            }
        }
        // ---- group barrier 1 (R5-proven) ----
        target += NJ;
        __syncthreads();
        if (tid == 0) {
            __threadfence();
            atomicAdd(&g_ctr[g], 1);
            while (ld_acq(&g_ctr[g]) < target) {}
            __threadfence();
        }
        __syncthreads();

        // prefetch z (CTA-private)
        float zz[4];
        #pragma unroll
        for (int rr = 0; rr < 4; rr++) {
            int rl = mt * 16 + (l >> 2) + ((rr >= 2) ? 8 : 0);
            int n2 = wn * 8 + (l & 3) * 2 + (rr & 1);
            zz[rr] = zOwn[rl * 32 + n2];
        }

        // ===== phase 2: cand = rh @ sWh =====
        float acc2[4] = {};
        {
            float4 pf[4];
            #pragma unroll
            for (int j = 0; j < 4; j++)
                pf[j] = __ldcg((const float4*)&g_rh[gofs[j]]);
            #pragma unroll
            for (int j = 0; j < 4; j++)
                *(float4*)&sSt0[sptr[j]] = pf[j];   // pre-rounded
            for (int pass = 0; pass < 4; pass++) {
                const int kb = pass * 128;
                if (pass < 3) {
                    #pragma unroll
                    for (int j = 0; j < 4; j++)
                        pf[j] = __ldcg((const float4*)&g_rh[gofs[j] + kb + 128]);
                }
                __syncthreads();
                const float* st = (pass & 1) ? sSt1 : sSt0;
                #pragma unroll
                for (int ks = 0; ks < 16; ks++) {
                    int c0 = (ks * 8 + (l & 3)) ^ xr;
                    int c1 = (ks * 8 + (l & 3) + 4) ^ xr;
                    uint32_t a0 = __float_as_uint(st[arow * 128 + c0]);
                    uint32_t a1 = __float_as_uint(st[(arow + 8) * 128 + c0]);
                    uint32_t a2 = __float_as_uint(st[arow * 128 + c1]);
                    uint32_t a3 = __float_as_uint(st[(arow + 8) * 128 + c1]);
                    const int kg = kb + ks * 8 + (l & 3);
                    const int sw = (kg & 3) * 8;
                    int n = (wn * 8 + (l >> 2)) ^ sw;
                    uint32_t b0 = __float_as_uint(sWh[kg * 32 + n]);
                    uint32_t b1 = __float_as_uint(sWh[(kg + 4) * 32 + n]);
                    MMA_TF32(acc2, a0, a1, a2, a3, b0, b1);
                }
                if (pass < 3) {
                    float* dst = (pass & 1) ? sSt0 : sSt1;
                    #pragma unroll
                    for (int j = 0; j < 4; j++)
                        *(float4*)&dst[sptr[j]] = pf[j];
                }
            }
        }
        #pragma unroll
        for (int rr = 0; rr < 4; rr++) {
            int row = (rr < 2) ? row0 : (row0 + 8);
            int rl  = mt * 16 + (l >> 2) + ((rr >= 2) ? 8 : 0);
            int n2  = wn * 8 + (l & 3) * 2 + (rr & 1);
            int col = jt * 32 + n2;
            float cand = tanhf(acc2[rr] + ew2[rr] + bhv[rr & 1]);
            float hn = fmaf(zz[rr], cand - hreg[rr], hreg[rr]);
            hreg[rr] = hn;
            hOwn[rl * 32 + n2] = hn;
            float hr = f2tff(hn);
            __stcg(&g_hR[row * 512 + col], hr);
            __stcg(&g_Hs[((size_t)row * Sn + t) * 512 + col], hr);
            if (t == Sn - 1) hOut[row * 512 + col] = hn;
        }
        // ---- group barrier 2 ----
        target += NJ;
        __syncthreads();
        if (tid == 0) {
            __threadfence();
            atomicAdd(&g_ctr[g], 1);
            while (ld_acq(&g_ctr[g]) < target) {}
            __threadfence();
        }
        __syncthreads();
    }
}

// ---------------- entry ------------------------------------------------------
extern "C" void kernel_launch(void* const* d_in, const int* in_sizes, int n_in,
                              void* d_out, int out_size) {
    const int*   x   = (const int*)  d_in[0];
    const float* emb = (const float*)d_in[1];
    const float* Wg  = (const float*)d_in[2];
    const float* bg  = (const float*)d_in[3];
    const float* Wh  = (const float*)d_in[4];
    const float* bh  = (const float*)d_in[5];
    const float* Wo  = (const float*)d_in[6];
    const float* bo  = (const float*)d_in[7];
    float* out = (float*)d_out;

    float *pEmbW, *pEmbR, *pWxT, *pWoT, *pHs;
    cudaGetSymbolAddress((void**)&pEmbW, g_EmbW);
    cudaGetSymbolAddress((void**)&pEmbR, g_embR);
    cudaGetSymbolAddress((void**)&pWxT,  g_WxT);
    cudaGetSymbolAddress((void**)&pWoT,  g_WoT);
    cudaGetSymbolAddress((void**)&pHs,   g_Hs);

    cudaFuncSetAttribute(gru_persistent,
                         cudaFuncAttributeMaxDynamicSharedMemorySize, SMEM_BYTES);

    pack_weights<<<7168, 256>>>(Wg, Wh, Wo);
    round_zero<<<(Vn * Hn + 255) / 256, 256>>>(emb);
    gemm_db<<<dim3(N1 / 128, (Vn + 127) / 128), 256>>>(pEmbR, pWxT, pEmbW, nullptr,
                                                       Vn, N1, Hn);
    gru_persistent<<<128, 256, SMEM_BYTES>>>(x, bg, bh, out);
    gemm_db<<<dim3(On / 128, (Bn * Sn) / 128), 256>>>(pHs, pWoT, out + Bn * Hn, bo,
                                                      Bn * Sn, On, Hn);
}

// round 11
// speedup vs baseline: 1.7292x; 1.0648x over previous
#include <cuda_runtime.h>
#include <math.h>
#include <stdint.h>

#define Vn 10000
#define Hn 512
#define On 512
#define Bn 256
#define Sn 256
#define N1 1536

#define NJ 16
#define NG 8
#define RB 32
// smem floats: sWgz2[32768] + sWh2[16384] + 2 x sSt[4224] (frag-major, pitch 132)
#define SMEM_BYTES ((32768 + 16384 + 2 * 4224) * 4)

// ---------------- scratch ----------------------------------------------------
__device__ float g_EmbW[(size_t)Vn * N1];
__device__ float g_embR[(size_t)Vn * Hn];      // tf32-rounded emb
__device__ float g_WxT [Hn * N1];              // tf32-rounded
__device__ float g_WgHt[Hn * 1024];
__device__ float g_WhHt[Hn * Hn];
__device__ float g_WoT [Hn * On];              // tf32-rounded
__device__ float g_hR  [Bn * Hn];              // rounded h (cross-CTA A operand)
__device__ float g_rh  [Bn * Hn];              // rounded r*h (cross-CTA)
__device__ float g_Hs  [(size_t)Bn * Sn * Hn]; // rounded hidden states
__device__ float g_zOwn[128 * RB * 32];        // CTA-private z (exact)
__device__ float g_hOwn[128 * RB * 32];        // CTA-private h (exact)
__device__ int   g_ctr [NG];

// ---------------- helpers ----------------------------------------------------
__device__ __forceinline__ float f2tff(float f) {
    uint32_t u; asm("cvt.rna.tf32.f32 %0, %1;" : "=r"(u) : "f"(f));
    return __uint_as_float(u);
}
#define MMA_TF32(C, a0,a1,a2,a3, b0,b1)                                        \
    asm volatile("mma.sync.aligned.m16n8k8.row.col.f32.tf32.tf32.f32 "         \
                 "{%0,%1,%2,%3}, {%4,%5,%6,%7}, {%8,%9}, {%0,%1,%2,%3};"       \
                 : "+f"((C)[0]), "+f"((C)[1]), "+f"((C)[2]), "+f"((C)[3])      \
                 : "r"(a0), "r"(a1), "r"(a2), "r"(a3), "r"(b0), "r"(b1))

__device__ __forceinline__ uint32_t s2u(const void* p) {
    return (uint32_t)__cvta_generic_to_shared(p);
}
__device__ __forceinline__ void cp16(uint32_t dst, const void* src, bool pred) {
    int sz = pred ? 16 : 0;
    asm volatile("cp.async.cg.shared.global [%0], [%1], 16, %2;"
                 :: "r"(dst), "l"(src), "r"(sz) : "memory");
}
#define CP_COMMIT() asm volatile("cp.async.commit_group;" ::: "memory")
#define CP_WAIT1()  asm volatile("cp.async.wait_group 1;" ::: "memory")

__device__ __forceinline__ int ld_acq(const int* p) {
    int v; asm volatile("ld.acquire.gpu.global.s32 %0, [%1];" : "=r"(v) : "l"(p) : "memory");
    return v;
}

// ---------------- weight packing ---------------------------------------------
__global__ void pack_weights(const float* __restrict__ Wg,
                             const float* __restrict__ Wh,
                             const float* __restrict__ Wo) {
    int idx = blockIdx.x * blockDim.x + threadIdx.x;
    const int s1 = Hn * N1, s2 = Hn * 1024, s3 = Hn * Hn, s4 = Hn * On;
    if (idx < s1) {
        int k = idx / N1, n = idx % N1;
        g_WxT[idx] = f2tff((n < 1024) ? Wg[n * 1024 + k] : Wh[(n - 1024) * 1024 + k]);
    } else if (idx < s1 + s2) {
        int r = idx - s1; int k = r / 1024, j = r % 1024;
        g_WgHt[r] = Wg[j * 1024 + 512 + k];
    } else if (idx < s1 + s2 + s3) {
        int r = idx - s1 - s2; int k = r / 512, j = r % 512;
        g_WhHt[r] = Wh[j * 1024 + 512 + k];
    } else if (idx < s1 + s2 + s3 + s4) {
        int r = idx - s1 - s2 - s3; int k = r / 512, o = r % 512;
        g_WoT[r] = f2tff(Wo[o * 512 + k]);
    }
}

// round emb + zero state/flags
__global__ void round_zero(const float* __restrict__ emb) {
    int i = blockIdx.x * blockDim.x + threadIdx.x;
    if (i < Vn * Hn) g_embR[i] = f2tff(emb[i]);
    if (i < Bn * Hn) g_hR[i] = 0.f;
    if (i < 128 * RB * 32) g_hOwn[i] = 0.f;
    if (i < NG) g_ctr[i] = 0;
}

// ------- double-buffered tf32 GEMM: C[M,N] = A[M,K] @ Bt[K,N] (+bias) -------
__global__ void __launch_bounds__(256)
gemm_db(const float* __restrict__ A, const float* __restrict__ Bt,
        float* __restrict__ C, const float* __restrict__ bias,
        int M, int N, int K) {
    __shared__ float As[2][128 * 20];
    __shared__ float Bs[2][16 * 136];
    const int tid = threadIdx.x, w = tid >> 5, l = tid & 31;
    const int wm = w >> 2, wn = w & 3;
    const int mBase = blockIdx.y * 128, nBase = blockIdx.x * 128;

    const int ar = tid >> 1, ac = (tid & 1) * 8;
    const int br = tid >> 4, bc = (tid & 15) * 4;

    auto stage = [&](int s, int k0) {
        bool pA = (mBase + ar) < M;
        const float* srcA = &A[(size_t)(mBase + ar) * K + k0 + ac];
        cp16(s2u(&As[s][ar * 20 + ac]),     srcA,     pA);
        cp16(s2u(&As[s][ar * 20 + ac + 4]), srcA + 4, pA);
        const float* srcB = &Bt[(size_t)(k0 + br) * N + nBase + bc];
        cp16(s2u(&Bs[s][br * 136 + bc]),      srcB,      true);
        cp16(s2u(&Bs[s][br * 136 + bc + 64]), srcB + 64, true);
    };

    float acc[4][4][4] = {};
    const int nIter = K / 16;
    stage(0, 0); CP_COMMIT();
    for (int it = 0; it < nIter; it++) {
        if (it + 1 < nIter) stage((it + 1) & 1, (it + 1) * 16);
        CP_COMMIT();
        CP_WAIT1();
        __syncthreads();
        const float* as = As[it & 1];
        const float* bs = Bs[it & 1];
        #pragma unroll
        for (int ks = 0; ks < 2; ks++) {
            const int kk = ks * 8 + (l & 3);
            uint32_t bfr[4][2];
            #pragma unroll
            for (int nt = 0; nt < 4; nt++) {
                int n = wn * 32 + nt * 8 + (l >> 2);
                bfr[nt][0] = __float_as_uint(bs[kk * 136 + n]);
                bfr[nt][1] = __float_as_uint(bs[(kk + 4) * 136 + n]);
            }
            #pragma unroll
            for (int mt = 0; mt < 4; mt++) {
                int r = wm * 64 + mt * 16 + (l >> 2);
                uint32_t a0 = __float_as_uint(as[r * 20 + kk]);
                uint32_t a1 = __float_as_uint(as[(r + 8) * 20 + kk]);
                uint32_t a2 = __float_as_uint(as[r * 20 + kk + 4]);
                uint32_t a3 = __float_as_uint(as[(r + 8) * 20 + kk + 4]);
                #pragma unroll
                for (int nt = 0; nt < 4; nt++)
                    MMA_TF32(acc[mt][nt], a0, a1, a2, a3, bfr[nt][0], bfr[nt][1]);
            }
        }
        __syncthreads();
    }
    #pragma unroll
    for (int mt = 0; mt < 4; mt++) {
        #pragma unroll
        for (int nt = 0; nt < 4; nt++) {
            #pragma unroll
            for (int rr = 0; rr < 4; rr++) {
                int row = mBase + wm * 64 + mt * 16 + (l >> 2) + ((rr >= 2) ? 8 : 0);
                if (row >= M) continue;
                int col = nBase + wn * 32 + nt * 8 + (l & 3) * 2 + (rr & 1);
                float v = acc[mt][nt][rr];
                if (bias) v += bias[col];
                C[(size_t)row * N + col] = v;
            }
        }
    }
}

// ------- persistent GRU: frag-major staging + paired weights -----------------
__global__ void __launch_bounds__(256, 1)
gru_persistent(const int* __restrict__ x, const float* __restrict__ bg,
               const float* __restrict__ bh, float* __restrict__ hOut) {
    extern __shared__ float sm[];
    float* sWgz = sm;                           // float2 pairs: [64 ko][4 klow][64 n^]
    float* sWh  = sWgz + 32768;                 // float2 pairs: [64 ko][4 klow][32 n^]
    float* sSt0 = sWh + 16384;                  // frag-major [32 blk][132]
    float* sSt1 = sSt0 + 4224;

    const int jt  = blockIdx.x & 15;
    const int g   = blockIdx.x >> 4;
    const int tid = threadIdx.x;
    const int w   = tid >> 5, l = tid & 31;
    const int mt  = w & 1;
    const int wn  = w >> 1;
    const int bBase = g * RB;

    float* zOwn = g_zOwn + blockIdx.x * (RB * 32);
    float* hOwn = g_hOwn + blockIdx.x * (RB * 32);

    // --- pack weights: (W[k][n], W[k+4][n]) pairs, XOR-swizzled by klow<<2 ---
    for (int i = tid; i < 64 * 4 * 64; i += 256) {   // sWgz pairs
        int n = i & 63, klow = (i >> 6) & 3, ko = i >> 8;
        int kg = ko * 8 + klow;
        int gcol = (n < 32) ? (512 + jt * 32 + n) : (jt * 32 + n - 32);
        float w0 = f2tff(g_WgHt[kg * 1024 + gcol]);
        float w1 = f2tff(g_WgHt[(kg + 4) * 1024 + gcol]);
        int f2i = ((ko * 4 + klow) << 6) + (n ^ (klow << 2));
        sWgz[f2i * 2]     = w0;
        sWgz[f2i * 2 + 1] = w1;
    }
    for (int i = tid; i < 64 * 4 * 32; i += 256) {   // sWh pairs
        int n = i & 31, klow = (i >> 5) & 3, ko = i >> 7;
        int kg = ko * 8 + klow;
        float w0 = f2tff(g_WhHt[kg * 512 + jt * 32 + n]);
        float w1 = f2tff(g_WhHt[(kg + 4) * 512 + jt * 32 + n]);
        int f2i = ((ko * 4 + klow) << 5) + (n ^ (klow << 2));
        sWh[f2i * 2]     = w0;
        sWh[f2i * 2 + 1] = w1;
    }
    __syncthreads();

    const int row0 = bBase + mt * 16 + (l >> 2);
    float bgv[4], bhv[2];
    #pragma unroll
    for (int ti = 0; ti < 2; ti++)
        #pragma unroll
        for (int p = 0; p < 2; p++) {
            int n = wn * 16 + ti * 8 + (l & 3) * 2 + p;
            int gcol = (n < 32) ? (512 + jt * 32 + n) : (jt * 32 + n - 32);
            bgv[ti * 2 + p] = bg[gcol];
        }
    #pragma unroll
    for (int p = 0; p < 2; p++)
        bhv[p] = bh[jt * 32 + wn * 8 + (l & 3) * 2 + p];

    // staging: warp w stages rows r = w + 8j, k-quad kq = 4l
    // frag-major write base: blk = (r>>4)*16 + (l>>1), pitch 132
    int gofs[4], wbase[4];
    #pragma unroll
    for (int j = 0; j < 4; j++) {
        int r = w + 8 * j;
        gofs[j]  = (bBase + r) * 512 + 4 * l;
        wbase[j] = ((r >> 4) * 16 + (l >> 1)) * 132 + (r & 7) * 16
                 + ((r >> 3) & 1) + 2 * (l & 1);
    }
    const int klow = l & 3;
    const int nx   = klow << 2;
    // precomputed b float2 indices (without ko term)
    const int bn0 = (wn * 16 + 0 + (l >> 2)) ^ nx;     // phase1 ti=0
    const int bn1 = (wn * 16 + 8 + (l >> 2)) ^ nx;     // phase1 ti=1
    const int bn2 = (wn * 8 + (l >> 2)) ^ nx;          // phase2
    const int fl2 = klow;                              // pair-slot within ko block

    float hreg[4] = {0.f, 0.f, 0.f, 0.f};
    int target = 0;

    for (int t = 0; t < Sn; t++) {
        const int tok0 = __ldg(&x[row0 * Sn + t]);
        const int tok1 = __ldg(&x[(row0 + 8) * Sn + t]);

        float ew1[8], hv1[8], ew2[4];
        #pragma unroll
        for (int ti = 0; ti < 2; ti++)
            #pragma unroll
            for (int rr = 0; rr < 4; rr++) {
                int tok = (rr < 2) ? tok0 : tok1;
                int n = wn * 16 + ti * 8 + (l & 3) * 2 + (rr & 1);
                int gcol = (n < 32) ? (512 + jt * 32 + n) : (jt * 32 + n - 32);
                ew1[ti * 4 + rr] = __ldg(&g_EmbW[(size_t)tok * N1 + gcol]);
                int rl = mt * 16 + (l >> 2) + ((rr >= 2) ? 8 : 0);
                hv1[ti * 4 + rr] = hOwn[rl * 32 + (n & 31)];
            }
        #pragma unroll
        for (int rr = 0; rr < 4; rr++) {
            int tok = (rr < 2) ? tok0 : tok1;
            int n2 = wn * 8 + (l & 3) * 2 + (rr & 1);
            ew2[rr] = __ldg(&g_EmbW[(size_t)tok * N1 + 1024 + jt * 32 + n2]);
        }

        // ===== phase 1: (r|z) = h @ Wgz =====
        float acc[8] = {};
        {
            float4 pf[4];
            #pragma unroll
            for (int j = 0; j < 4; j++)
                pf[j] = __ldcg((const float4*)&g_hR[gofs[j]]);
            #pragma unroll
            for (int j = 0; j < 4; j++) {
                sSt0[wbase[j] + 0]  = pf[j].x;
                sSt0[wbase[j] + 4]  = pf[j].y;
                sSt0[wbase[j] + 8]  = pf[j].z;
                sSt0[wbase[j] + 12] = pf[j].w;
            }
            for (int pass = 0; pass < 4; pass++) {
                if (pass < 3) {
                    #pragma unroll
                    for (int j = 0; j < 4; j++)
                        pf[j] = __ldcg((const float4*)&g_hR[gofs[j] + pass * 128 + 128]);
                }
                __syncthreads();
                const float4* st4 = (const float4*)((pass & 1) ? sSt1 : sSt0);
                const int kob = pass * 16;
                #pragma unroll
                for (int ks = 0; ks < 16; ks++) {
                    float4 av = st4[(mt * 16 + ks) * 33 + l];
                    uint32_t a0 = __float_as_uint(av.x);
                    uint32_t a1 = __float_as_uint(av.y);
                    uint32_t a2 = __float_as_uint(av.z);
                    uint32_t a3 = __float_as_uint(av.w);
                    const int kblk = ((kob + ks) * 4 + fl2);
                    float2 bv0 = *(const float2*)&sWgz[((kblk << 6) + bn0) * 2];
                    float2 bv1 = *(const float2*)&sWgz[((kblk << 6) + bn1) * 2];
                    MMA_TF32(acc,     a0, a1, a2, a3,
                             __float_as_uint(bv0.x), __float_as_uint(bv0.y));
                    MMA_TF32(acc + 4, a0, a1, a2, a3,
                             __float_as_uint(bv1.x), __float_as_uint(bv1.y));
                }
                if (pass < 3) {
                    float* dst = (pass & 1) ? sSt0 : sSt1;
                    #pragma unroll
                    for (int j = 0; j < 4; j++) {
                        dst[wbase[j] + 0]  = pf[j].x;
                        dst[wbase[j] + 4]  = pf[j].y;
                        dst[wbase[j] + 8]  = pf[j].z;
                        dst[wbase[j] + 12] = pf[j].w;
                    }
                }
            }
        }
        #pragma unroll
        for (int ti = 0; ti < 2; ti++) {
            #pragma unroll
            for (int rr = 0; rr < 4; rr++) {
                int row = (rr < 2) ? row0 : (row0 + 8);
                int rl  = mt * 16 + (l >> 2) + ((rr >= 2) ? 8 : 0);
                int n = wn * 16 + ti * 8 + (l & 3) * 2 + (rr & 1);
                float gv = acc[ti * 4 + rr] + ew1[ti * 4 + rr] + bgv[ti * 2 + (rr & 1)];
                float s = 1.f / (1.f + __expf(-gv));
                if (n < 32) {
                    __stcg(&g_rh[row * 512 + jt * 32 + n], f2tff(s * hv1[ti * 4 + rr]));
                } else {
                    zOwn[rl * 32 + (n - 32)] = s;
                }
            }
        }
        // ---- group barrier 1 ----
        target += NJ;
        __syncthreads();
        if (tid == 0) {
            __threadfence();
            atomicAdd(&g_ctr[g], 1);
            while (ld_acq(&g_ctr[g]) < target) {}
            __threadfence();
        }
        __syncthreads();

        float zz[4];
        #pragma unroll
        for (int rr = 0; rr < 4; rr++) {
            int rl = mt * 16 + (l >> 2) + ((rr >= 2) ? 8 : 0);
            int n2 = wn * 8 + (l & 3) * 2 + (rr & 1);
            zz[rr] = zOwn[rl * 32 + n2];
        }

        // ===== phase 2: cand = rh @ Wh =====
        float acc2[4] = {};
        {
            float4 pf[4];
            #pragma unroll
            for (int j = 0; j < 4; j++)
                pf[j] = __ldcg((const float4*)&g_rh[gofs[j]]);
            #pragma unroll
            for (int j = 0; j < 4; j++) {
                sSt0[wbase[j] + 0]  = pf[j].x;
                sSt0[wbase[j] + 4]  = pf[j].y;
                sSt0[wbase[j] + 8]  = pf[j].z;
                sSt0[wbase[j] + 12] = pf[j].w;
            }
            for (int pass = 0; pass < 4; pass++) {
                if (pass < 3) {
                    #pragma unroll
                    for (int j = 0; j < 4; j++)
                        pf[j] = __ldcg((const float4*)&g_rh[gofs[j] + pass * 128 + 128]);
                }
                __syncthreads();
                const float4* st4 = (const float4*)((pass & 1) ? sSt1 : sSt0);
                const int kob = pass * 16;
                #pragma unroll
                for (int ks = 0; ks < 16; ks++) {
                    float4 av = st4[(mt * 16 + ks) * 33 + l];
                    uint32_t a0 = __float_as_uint(av.x);
                    uint32_t a1 = __float_as_uint(av.y);
                    uint32_t a2 = __float_as_uint(av.z);
                    uint32_t a3 = __float_as_uint(av.w);
                    const int kblk = ((kob + ks) * 4 + fl2);
                    float2 bv = *(const float2*)&sWh[((kblk << 5) + bn2) * 2];
                    MMA_TF32(acc2, a0, a1, a2, a3,
                             __float_as_uint(bv.x), __float_as_uint(bv.y));
                }
                if (pass < 3) {
                    float* dst = (pass & 1) ? sSt0 : sSt1;
                    #pragma unroll
                    for (int j = 0; j < 4; j++) {
                        dst[wbase[j] + 0]  = pf[j].x;
                        dst[wbase[j] + 4]  = pf[j].y;
                        dst[wbase[j] + 8]  = pf[j].z;
                        dst[wbase[j] + 12] = pf[j].w;
                    }
                }
            }
        }
        #pragma unroll
        for (int rr = 0; rr < 4; rr++) {
            int row = (rr < 2) ? row0 : (row0 + 8);
            int rl  = mt * 16 + (l >> 2) + ((rr >= 2) ? 8 : 0);
            int n2  = wn * 8 + (l & 3) * 2 + (rr & 1);
            int col = jt * 32 + n2;
            float cand = tanhf(acc2[rr] + ew2[rr] + bhv[rr & 1]);
            float hn = fmaf(zz[rr], cand - hreg[rr], hreg[rr]);
            hreg[rr] = hn;
            hOwn[rl * 32 + n2] = hn;
            float hr = f2tff(hn);
            __stcg(&g_hR[row * 512 + col], hr);
            __stcg(&g_Hs[((size_t)row * Sn + t) * 512 + col], hr);
            if (t == Sn - 1) hOut[row * 512 + col] = hn;
        }
        // ---- group barrier 2 ----
        target += NJ;
        __syncthreads();
        if (tid == 0) {
            __threadfence();
            atomicAdd(&g_ctr[g], 1);
            while (ld_acq(&g_ctr[g]) < target) {}
            __threadfence();
        }
        __syncthreads();
    }
}

// ---------------- entry ------------------------------------------------------
extern "C" void kernel_launch(void* const* d_in, const int* in_sizes, int n_in,
                              void* d_out, int out_size) {
    const int*   x   = (const int*)  d_in[0];
    const float* emb = (const float*)d_in[1];
    const float* Wg  = (const float*)d_in[2];
    const float* bg  = (const float*)d_in[3];
    const float* Wh  = (const float*)d_in[4];
    const float* bh  = (const float*)d_in[5];
    const float* Wo  = (const float*)d_in[6];
    const float* bo  = (const float*)d_in[7];
    float* out = (float*)d_out;

    float *pEmbW, *pEmbR, *pWxT, *pWoT, *pHs;
    cudaGetSymbolAddress((void**)&pEmbW, g_EmbW);
    cudaGetSymbolAddress((void**)&pEmbR, g_embR);
    cudaGetSymbolAddress((void**)&pWxT,  g_WxT);
    cudaGetSymbolAddress((void**)&pWoT,  g_WoT);
    cudaGetSymbolAddress((void**)&pHs,   g_Hs);

    cudaFuncSetAttribute(gru_persistent,
                         cudaFuncAttributeMaxDynamicSharedMemorySize, SMEM_BYTES);

    pack_weights<<<7168, 256>>>(Wg, Wh, Wo);
    round_zero<<<(Vn * Hn + 255) / 256, 256>>>(emb);
    gemm_db<<<dim3(N1 / 128, (Vn + 127) / 128), 256>>>(pEmbR, pWxT, pEmbW, nullptr,
                                                       Vn, N1, Hn);
    gru_persistent<<<128, 256, SMEM_BYTES>>>(x, bg, bh, out);
    gemm_db<<<dim3(On / 128, (Bn * Sn) / 128), 256>>>(pHs, pWoT, out + Bn * Hn, bo,
                                                      Bn * Sn, On, Hn);
}